// round 1
// baseline (speedup 1.0000x reference)
#include <cuda_runtime.h>
#include <math.h>

#define Bc   16
#define Sc   256
#define Dc   256
#define Hc   128
#define DKc  64
#define NIN  512    // SRU input width (out ++ pools)
#define NJ   1024   // fwd 4H ++ bwd 4H
#define GRP  8      // s-rows per attention block

// ---------------- scratch (device globals; no allocation allowed) -------------
__device__ float g_xtT[Bc * DKc * Sc];     // [b][k][l]  : xt transposed
__device__ float g_out[Sc * Bc * Dc];      // [s][b][d]  : layer output
__device__ float g_inputs[Sc * Bc * NIN];  // [s][b][512]: cat(out, pools)
__device__ float g_U[Sc * Bc * NJ];        // [s][b][1024]

__device__ __forceinline__ float tanh_fast(float x) {
    float y;
    asm("tanh.approx.f32 %0, %1;" : "=f"(y) : "f"(x));
    return y;
}

// ---------------------------------------------------------------------------
// xtT[b][k][l] = b1[a,k] + sum_d x[b,l,d] * w1[a,d,k]   (computed once)
// grid (16, 4) : (b, 64-row l tile). block 256. 64x64 tile, BK=32, 4x4 micro.
// ---------------------------------------------------------------------------
__global__ void k_xt(const float* __restrict__ x, const float* __restrict__ w1,
                     const float* __restrict__ b1, const int* __restrict__ act) {
    const int b  = blockIdx.x;
    const int lt = blockIdx.y;
    const int a  = act[b];
    const float* xb = x  + b * Sc * Dc + lt * 64 * Dc;
    const float* wa = w1 + a * Dc * DKc;

    __shared__ float xs[32][65];   // [d][l]
    __shared__ float ws[32][64];   // [d][k]

    const int tid = threadIdx.x;
    const int ty = tid >> 4, tx = tid & 15;
    float acc[4][4] = {};

    for (int d0 = 0; d0 < Dc; d0 += 32) {
        for (int i = tid; i < 64 * 32; i += 256) {
            int l = i >> 5, d = i & 31;
            xs[d][l] = xb[l * Dc + d0 + d];
        }
        for (int i = tid; i < 32 * 64; i += 256) {
            int d = i >> 6, k = i & 63;
            ws[d][k] = wa[(d0 + d) * DKc + k];
        }
        __syncthreads();
#pragma unroll
        for (int d = 0; d < 32; d++) {
            float af[4], bfv[4];
#pragma unroll
            for (int i = 0; i < 4; i++) af[i] = xs[d][ty * 4 + i];
#pragma unroll
            for (int j = 0; j < 4; j++) bfv[j] = ws[d][tx * 4 + j];
#pragma unroll
            for (int i = 0; i < 4; i++)
#pragma unroll
                for (int j = 0; j < 4; j++) acc[i][j] = fmaf(af[i], bfv[j], acc[i][j]);
        }
        __syncthreads();
    }
#pragma unroll
    for (int j = 0; j < 4; j++) {
        int k = tx * 4 + j;
        float bb = b1[a * DKc + k];
#pragma unroll
        for (int i = 0; i < 4; i++) {
            int l = lt * 64 + ty * 4 + i;
            g_xtT[b * (DKc * Sc) + k * Sc + l] = acc[i][j] + bb;
        }
    }
}

// ---------------------------------------------------------------------------
// Attention for GRP=8 consecutive s rows of one batch b:
//   yt, tanh-scores vs all l, softmax, pools; writes cat(out,pools) rows to
//   g_inputs. grid (32, 16) = (s-tile, b), block 256.
// ---------------------------------------------------------------------------
__global__ void k_attn(const float* __restrict__ x, int layer0,
                       const unsigned char* __restrict__ mask,
                       const int* __restrict__ act,
                       const float* __restrict__ w2, const float* __restrict__ b2,
                       const float* __restrict__ v) {
    const int s0 = blockIdx.x * GRP;
    const int b  = blockIdx.y;
    const int a  = act[b];
    const int tid = threadIdx.x;

    __shared__ float row[GRP][Dc];                    // rnn-input rows (8KB)
    __shared__ float yt[GRP][DKc];
    __shared__ float vv[DKc];
    __shared__ __align__(16) float att[Sc][GRP];      // unnormalized attn (8KB)
    __shared__ float ytp[GRP][4][DKc];                // yt partials (8KB)
    __shared__ float red[8][GRP];
    __shared__ float gmax[GRP], ginv[GRP];

    // load the 8 rnn-input rows; also write them as first half of g_inputs
#pragma unroll
    for (int g = 0; g < GRP; g++) {
        int s = s0 + g;
        float val = layer0 ? x[b * Sc * Dc + s * Dc + tid]
                           : g_out[(s * Bc + b) * Dc + tid];
        row[g][tid] = val;
        g_inputs[(s * Bc + b) * NIN + tid] = val;
    }
    if (tid < DKc) vv[tid] = v[a * DKc + tid];
    __syncthreads();

    // yt[g][k] = b2[a,k] + sum_d row[g][d] * w2[a,d,k]
    {
        const float* wa = w2 + a * Dc * DKc;
        const int k = tid & 63, part = tid >> 6;
        float acc[GRP] = {};
        for (int i = 0; i < 64; i++) {
            int d = part * 64 + i;
            float w = wa[d * DKc + k];
#pragma unroll
            for (int g = 0; g < GRP; g++) acc[g] = fmaf(row[g][d], w, acc[g]);
        }
#pragma unroll
        for (int g = 0; g < GRP; g++) ytp[g][part][k] = acc[g];
    }
    __syncthreads();
    for (int idx = tid; idx < GRP * DKc; idx += 256) {
        int g = idx >> 6, k = idx & 63;
        yt[g][k] = ytp[g][0][k] + ytp[g][1][k] + ytp[g][2][k] + ytp[g][3][k]
                 + b2[a * DKc + k];
    }
    __syncthreads();

    // scores: this thread handles memory position l = tid for all 8 s rows
    float sc[GRP] = {};
    {
        const float* xt = g_xtT + b * (DKc * Sc);
#pragma unroll 4
        for (int k = 0; k < DKc; k++) {
            float xv = xt[k * Sc + tid];
            float vk = vv[k];
#pragma unroll
            for (int g = 0; g < GRP; g++)
                sc[g] = fmaf(vk, tanh_fast(xv + yt[g][k]), sc[g]);
        }
        if (mask[b * Sc + tid]) {
#pragma unroll
            for (int g = 0; g < GRP; g++) sc[g] = -1e30f;
        }
    }

    // softmax over l (block-wide), per g
    const int lane = tid & 31, wid = tid >> 5;
#pragma unroll
    for (int g = 0; g < GRP; g++) {
        float m = sc[g];
#pragma unroll
        for (int o = 16; o > 0; o >>= 1) m = fmaxf(m, __shfl_xor_sync(0xffffffffu, m, o));
        if (lane == 0) red[wid][g] = m;
    }
    __syncthreads();
    if (tid < GRP) {
        float m = red[0][tid];
#pragma unroll
        for (int w = 1; w < 8; w++) m = fmaxf(m, red[w][tid]);
        gmax[tid] = m;
    }
    __syncthreads();
    float ex[GRP];
#pragma unroll
    for (int g = 0; g < GRP; g++) {
        ex[g] = __expf(sc[g] - gmax[g]);
        att[tid][g] = ex[g];
    }
#pragma unroll
    for (int g = 0; g < GRP; g++) {
        float s = ex[g];
#pragma unroll
        for (int o = 16; o > 0; o >>= 1) s += __shfl_xor_sync(0xffffffffu, s, o);
        if (lane == 0) red[wid][g] = s;
    }
    __syncthreads();
    if (tid < GRP) {
        float s = red[0][tid];
#pragma unroll
        for (int w = 1; w < 8; w++) s += red[w][tid];
        ginv[tid] = 1.0f / s;
    }
    __syncthreads();

    // pools: this thread handles feature d = tid for all 8 s rows
    float p[GRP] = {};
    const float* xb = x + b * Sc * Dc;
#pragma unroll 2
    for (int l = 0; l < Sc; l++) {
        float xv = xb[l * Dc + tid];
        float4 a0 = *reinterpret_cast<const float4*>(&att[l][0]);
        float4 a1 = *reinterpret_cast<const float4*>(&att[l][4]);
        p[0] = fmaf(a0.x, xv, p[0]); p[1] = fmaf(a0.y, xv, p[1]);
        p[2] = fmaf(a0.z, xv, p[2]); p[3] = fmaf(a0.w, xv, p[3]);
        p[4] = fmaf(a1.x, xv, p[4]); p[5] = fmaf(a1.y, xv, p[5]);
        p[6] = fmaf(a1.z, xv, p[6]); p[7] = fmaf(a1.w, xv, p[7]);
    }
#pragma unroll
    for (int g = 0; g < GRP; g++) {
        int s = s0 + g;
        g_inputs[(s * Bc + b) * NIN + Dc + tid] = p[g] * ginv[g];
    }
}

// ---------------------------------------------------------------------------
// SRU projection GEMM: U[4096,1024] = inputs[4096,512] @ [Wf | Wb]
// BM=128, BN=64, BK=16, 256 threads, 8x4 micro-tile. grid (32, 16).
// ---------------------------------------------------------------------------
__global__ void k_sru_gemm(const float* __restrict__ wf, const float* __restrict__ wb,
                           int layer) {
    const int mt = blockIdx.x;          // 32 row tiles of 128
    const int n0 = blockIdx.y * 64;     // col tile
    const float* Wsrc = (n0 < 512) ? (wf + layer * NIN * 512 + n0)
                                   : (wb + layer * NIN * 512 + (n0 - 512));
    const float* Arow = g_inputs + mt * 128 * NIN;

    __shared__ __align__(16) float As[16][132];   // [d][m]
    __shared__ __align__(16) float Bs[16][64];    // [d][j]

    const int tid = threadIdx.x;
    const int ty = tid >> 4, tx = tid & 15;       // 16x16
    float acc[8][4] = {};

    for (int d0 = 0; d0 < NIN; d0 += 16) {
        for (int i = tid; i < 128 * 16; i += 256) {
            int m = i >> 4, d = i & 15;
            As[d][m] = Arow[m * NIN + d0 + d];
        }
        for (int i = tid; i < 16 * 64; i += 256) {
            int d = i >> 6, j = i & 63;
            Bs[d][j] = Wsrc[(d0 + d) * 512 + j];
        }
        __syncthreads();
#pragma unroll
        for (int d = 0; d < 16; d++) {
            float4 a0 = *reinterpret_cast<const float4*>(&As[d][ty * 8]);
            float4 a1 = *reinterpret_cast<const float4*>(&As[d][ty * 8 + 4]);
            float4 bq = *reinterpret_cast<const float4*>(&Bs[d][tx * 4]);
            float af[8] = {a0.x, a0.y, a0.z, a0.w, a1.x, a1.y, a1.z, a1.w};
            float bv[4] = {bq.x, bq.y, bq.z, bq.w};
#pragma unroll
            for (int i = 0; i < 8; i++)
#pragma unroll
                for (int j = 0; j < 4; j++)
                    acc[i][j] = fmaf(af[i], bv[j], acc[i][j]);
        }
        __syncthreads();
    }
    float* Crow = g_U + (mt * 128) * NJ + n0;
#pragma unroll
    for (int i = 0; i < 8; i++) {
        float4 o = make_float4(acc[i][0], acc[i][1], acc[i][2], acc[i][3]);
        *reinterpret_cast<float4*>(&Crow[(ty * 8 + i) * NJ + tx * 4]) = o;
    }
}

// ---------------------------------------------------------------------------
// SRU recurrence, both "directions" (both are forward scans in the reference).
// grid 32 = (b, dir), block 128 = h.
// ---------------------------------------------------------------------------
__global__ void k_scan(const float* __restrict__ bfv, const float* __restrict__ bbv,
                       int layer, int is_last, float* __restrict__ out_final) {
    const int b   = blockIdx.x >> 1;
    const int dir = blockIdx.x & 1;
    const int h   = threadIdx.x;
    const float* bias = (dir == 0 ? bfv : bbv) + layer * 2 * Hc;
    const float bf = bias[h];
    const float br = bias[Hc + h];
    const int jb = dir * 512 + h;

    float c = 0.0f;
#pragma unroll 4
    for (int s = 0; s < Sc; s++) {
        const float* u = g_U + (s * Bc + b) * NJ + jb;
        float u0 = u[0];
        float uf = u[128];
        float ur = u[256];
        float hw = u[384];
        float f = 1.0f / (1.0f + __expf(-(uf + bf)));
        float r = 1.0f / (1.0f + __expf(-(ur + br)));
        c = u0 + f * (c - u0);                 // f*c + (1-f)*u0
        float hv = hw + r * (tanhf(c) - hw);   // r*tanh(c) + (1-r)*hw
        if (is_last)
            out_final[b * (Sc * Dc) + s * Dc + dir * Hc + h] = hv;
        else
            g_out[(s * Bc + b) * Dc + dir * Hc + h] = hv;
    }
}

// ---------------------------------------------------------------------------
extern "C" void kernel_launch(void* const* d_in, const int* in_sizes, int n_in,
                              void* d_out, int out_size) {
    const float* x            = (const float*)d_in[0];
    const unsigned char* mask = (const unsigned char*)d_in[1];
    const int* act            = (const int*)d_in[2];
    const float* w1           = (const float*)d_in[3];
    const float* b1           = (const float*)d_in[4];
    const float* w2           = (const float*)d_in[5];
    const float* b2           = (const float*)d_in[6];
    const float* v            = (const float*)d_in[7];
    const float* swf          = (const float*)d_in[8];
    const float* sbf          = (const float*)d_in[9];
    const float* swb          = (const float*)d_in[10];
    const float* sbb          = (const float*)d_in[11];
    float* out = (float*)d_out;

    // xt depends only on x/w1 -> once for both layers
    k_xt<<<dim3(Bc, 4), 256>>>(x, w1, b1, act);

    for (int layer = 0; layer < 2; layer++) {
        k_attn<<<dim3(Sc / GRP, Bc), 256>>>(x, layer == 0 ? 1 : 0, mask, act, w2, b2, v);
        k_sru_gemm<<<dim3(32, 16), 256>>>(swf, swb, layer);
        k_scan<<<32, 128>>>(sbf, sbb, layer, layer == 1 ? 1 : 0, out);
    }
}

// round 2
// speedup vs baseline: 1.4207x; 1.4207x over previous
#include <cuda_runtime.h>
#include <math.h>

#define Bc   16
#define Sc   256
#define Dc   256
#define Hc   128
#define DKc  64
#define NIN  512    // SRU input width (out ++ pools)
#define NJ   1024   // fwd 4H ++ bwd 4H
#define GRP  8      // s-rows per attention block
#define NCH  16     // scan chunks
#define CHS  16     // steps per chunk (NCH*CHS == Sc)

// ---------------- scratch (device globals; no allocation allowed) -------------
__device__ float g_xtT[Bc * DKc * Sc];     // [b][k][l]  : xt transposed
__device__ float g_out[Sc * Bc * Dc];      // [s][b][d]  : layer output
__device__ float g_inputs[Sc * Bc * NIN];  // [s][b][512]: cat(out, pools)
__device__ float g_U[Sc * Bc * NJ];        // [s][b][1024]
__device__ float g_cend[NCH * 32 * Hc];    // scan chunk-local end state
__device__ float g_P[NCH * 32 * Hc];       // scan chunk decay product
__device__ float g_cin[NCH * 32 * Hc];     // scan chunk incoming state

__device__ __forceinline__ float tanh_fast(float x) {
    float y;
    asm("tanh.approx.f32 %0, %1;" : "=f"(y) : "f"(x));
    return y;
}
__device__ __forceinline__ float sig_fast(float x) {
    float e, r;
    asm("ex2.approx.f32 %0, %1;" : "=f"(e) : "f"(x * -1.4426950408889634f));
    asm("rcp.approx.f32 %0, %1;" : "=f"(r) : "f"(1.0f + e));
    return r;
}

// ---------------------------------------------------------------------------
// xtT[b][k][l] = b1[a,k] + sum_d x[b,l,d] * w1[a,d,k]   (computed once)
// ---------------------------------------------------------------------------
__global__ void k_xt(const float* __restrict__ x, const float* __restrict__ w1,
                     const float* __restrict__ b1, const int* __restrict__ act) {
    const int b  = blockIdx.x;
    const int lt = blockIdx.y;
    const int a  = act[b];
    const float* xb = x  + b * Sc * Dc + lt * 64 * Dc;
    const float* wa = w1 + a * Dc * DKc;

    __shared__ float xs[32][65];   // [d][l]
    __shared__ float ws[32][64];   // [d][k]

    const int tid = threadIdx.x;
    const int ty = tid >> 4, tx = tid & 15;
    float acc[4][4] = {};

    for (int d0 = 0; d0 < Dc; d0 += 32) {
        for (int i = tid; i < 64 * 32; i += 256) {
            int l = i >> 5, d = i & 31;
            xs[d][l] = xb[l * Dc + d0 + d];
        }
        for (int i = tid; i < 32 * 64; i += 256) {
            int d = i >> 6, k = i & 63;
            ws[d][k] = wa[(d0 + d) * DKc + k];
        }
        __syncthreads();
#pragma unroll
        for (int d = 0; d < 32; d++) {
            float af[4], bfv[4];
#pragma unroll
            for (int i = 0; i < 4; i++) af[i] = xs[d][ty * 4 + i];
#pragma unroll
            for (int j = 0; j < 4; j++) bfv[j] = ws[d][tx * 4 + j];
#pragma unroll
            for (int i = 0; i < 4; i++)
#pragma unroll
                for (int j = 0; j < 4; j++) acc[i][j] = fmaf(af[i], bfv[j], acc[i][j]);
        }
        __syncthreads();
    }
#pragma unroll
    for (int j = 0; j < 4; j++) {
        int k = tx * 4 + j;
        float bb = b1[a * DKc + k];
#pragma unroll
        for (int i = 0; i < 4; i++) {
            int l = lt * 64 + ty * 4 + i;
            g_xtT[b * (DKc * Sc) + k * Sc + l] = acc[i][j] + bb;
        }
    }
}

// ---------------------------------------------------------------------------
// Attention for GRP=8 consecutive s rows of one batch b.
// ---------------------------------------------------------------------------
__global__ void k_attn(const float* __restrict__ x, int layer0,
                       const unsigned char* __restrict__ mask,
                       const int* __restrict__ act,
                       const float* __restrict__ w2, const float* __restrict__ b2,
                       const float* __restrict__ v) {
    const int s0 = blockIdx.x * GRP;
    const int b  = blockIdx.y;
    const int a  = act[b];
    const int tid = threadIdx.x;

    __shared__ float row[GRP][Dc];
    __shared__ float yt[GRP][DKc];
    __shared__ float vv[DKc];
    __shared__ __align__(16) float att[Sc][GRP];
    __shared__ float ytp[GRP][4][DKc];
    __shared__ float red[8][GRP];
    __shared__ float gmax[GRP], ginv[GRP];

#pragma unroll
    for (int g = 0; g < GRP; g++) {
        int s = s0 + g;
        float val = layer0 ? x[b * Sc * Dc + s * Dc + tid]
                           : g_out[(s * Bc + b) * Dc + tid];
        row[g][tid] = val;
        g_inputs[(s * Bc + b) * NIN + tid] = val;
    }
    if (tid < DKc) vv[tid] = v[a * DKc + tid];
    __syncthreads();

    {
        const float* wa = w2 + a * Dc * DKc;
        const int k = tid & 63, part = tid >> 6;
        float acc[GRP] = {};
        for (int i = 0; i < 64; i++) {
            int d = part * 64 + i;
            float w = wa[d * DKc + k];
#pragma unroll
            for (int g = 0; g < GRP; g++) acc[g] = fmaf(row[g][d], w, acc[g]);
        }
#pragma unroll
        for (int g = 0; g < GRP; g++) ytp[g][part][k] = acc[g];
    }
    __syncthreads();
    for (int idx = tid; idx < GRP * DKc; idx += 256) {
        int g = idx >> 6, k = idx & 63;
        yt[g][k] = ytp[g][0][k] + ytp[g][1][k] + ytp[g][2][k] + ytp[g][3][k]
                 + b2[a * DKc + k];
    }
    __syncthreads();

    float sc[GRP] = {};
    {
        const float* xt = g_xtT + b * (DKc * Sc);
#pragma unroll 4
        for (int k = 0; k < DKc; k++) {
            float xv = xt[k * Sc + tid];
            float vk = vv[k];
#pragma unroll
            for (int g = 0; g < GRP; g++)
                sc[g] = fmaf(vk, tanh_fast(xv + yt[g][k]), sc[g]);
        }
        if (mask[b * Sc + tid]) {
#pragma unroll
            for (int g = 0; g < GRP; g++) sc[g] = -1e30f;
        }
    }

    const int lane = tid & 31, wid = tid >> 5;
#pragma unroll
    for (int g = 0; g < GRP; g++) {
        float m = sc[g];
#pragma unroll
        for (int o = 16; o > 0; o >>= 1) m = fmaxf(m, __shfl_xor_sync(0xffffffffu, m, o));
        if (lane == 0) red[wid][g] = m;
    }
    __syncthreads();
    if (tid < GRP) {
        float m = red[0][tid];
#pragma unroll
        for (int w = 1; w < 8; w++) m = fmaxf(m, red[w][tid]);
        gmax[tid] = m;
    }
    __syncthreads();
    float ex[GRP];
#pragma unroll
    for (int g = 0; g < GRP; g++) {
        ex[g] = __expf(sc[g] - gmax[g]);
        att[tid][g] = ex[g];
    }
#pragma unroll
    for (int g = 0; g < GRP; g++) {
        float s = ex[g];
#pragma unroll
        for (int o = 16; o > 0; o >>= 1) s += __shfl_xor_sync(0xffffffffu, s, o);
        if (lane == 0) red[wid][g] = s;
    }
    __syncthreads();
    if (tid < GRP) {
        float s = red[0][tid];
#pragma unroll
        for (int w = 1; w < 8; w++) s += red[w][tid];
        ginv[tid] = 1.0f / s;
    }
    __syncthreads();

    float p[GRP] = {};
    const float* xb = x + b * Sc * Dc;
#pragma unroll 2
    for (int l = 0; l < Sc; l++) {
        float xv = xb[l * Dc + tid];
        float4 a0 = *reinterpret_cast<const float4*>(&att[l][0]);
        float4 a1 = *reinterpret_cast<const float4*>(&att[l][4]);
        p[0] = fmaf(a0.x, xv, p[0]); p[1] = fmaf(a0.y, xv, p[1]);
        p[2] = fmaf(a0.z, xv, p[2]); p[3] = fmaf(a0.w, xv, p[3]);
        p[4] = fmaf(a1.x, xv, p[4]); p[5] = fmaf(a1.y, xv, p[5]);
        p[6] = fmaf(a1.z, xv, p[6]); p[7] = fmaf(a1.w, xv, p[7]);
    }
#pragma unroll
    for (int g = 0; g < GRP; g++) {
        int s = s0 + g;
        g_inputs[(s * Bc + b) * NIN + Dc + tid] = p[g] * ginv[g];
    }
}

// ---------------------------------------------------------------------------
// SRU projection GEMM: U[4096,1024] = inputs[4096,512] @ [Wf | Wb]
// ---------------------------------------------------------------------------
__global__ void k_sru_gemm(const float* __restrict__ wf, const float* __restrict__ wb,
                           int layer) {
    const int mt = blockIdx.x;
    const int n0 = blockIdx.y * 64;
    const float* Wsrc = (n0 < 512) ? (wf + layer * NIN * 512 + n0)
                                   : (wb + layer * NIN * 512 + (n0 - 512));
    const float* Arow = g_inputs + mt * 128 * NIN;

    __shared__ __align__(16) float As[16][132];
    __shared__ __align__(16) float Bs[16][64];

    const int tid = threadIdx.x;
    const int ty = tid >> 4, tx = tid & 15;
    float acc[8][4] = {};

    for (int d0 = 0; d0 < NIN; d0 += 16) {
        for (int i = tid; i < 128 * 16; i += 256) {
            int m = i >> 4, d = i & 15;
            As[d][m] = Arow[m * NIN + d0 + d];
        }
        for (int i = tid; i < 16 * 64; i += 256) {
            int d = i >> 6, j = i & 63;
            Bs[d][j] = Wsrc[(d0 + d) * 512 + j];
        }
        __syncthreads();
#pragma unroll
        for (int d = 0; d < 16; d++) {
            float4 a0 = *reinterpret_cast<const float4*>(&As[d][ty * 8]);
            float4 a1 = *reinterpret_cast<const float4*>(&As[d][ty * 8 + 4]);
            float4 bq = *reinterpret_cast<const float4*>(&Bs[d][tx * 4]);
            float af[8] = {a0.x, a0.y, a0.z, a0.w, a1.x, a1.y, a1.z, a1.w};
            float bv[4] = {bq.x, bq.y, bq.z, bq.w};
#pragma unroll
            for (int i = 0; i < 8; i++)
#pragma unroll
                for (int j = 0; j < 4; j++)
                    acc[i][j] = fmaf(af[i], bv[j], acc[i][j]);
        }
        __syncthreads();
    }
    float* Crow = g_U + (mt * 128) * NJ + n0;
#pragma unroll
    for (int i = 0; i < 8; i++) {
        float4 o = make_float4(acc[i][0], acc[i][1], acc[i][2], acc[i][3]);
        *reinterpret_cast<float4*>(&Crow[(ty * 8 + i) * NJ + tx * 4]) = o;
    }
}

// ---------------------------------------------------------------------------
// SRU scan, chunked-parallel (3 passes). The recurrence c_s = f*c + (1-f)*u
// is affine in c, so each 16-step chunk is (c_in -> P*c_in + c_end).
// Pass A: per-chunk (P, c_end) from c=0.  Pass B: compose 16 affine maps.
// Pass C: re-run each chunk seeded with c_in; emit h.
// ---------------------------------------------------------------------------
__global__ void k_scanA(const float* __restrict__ bfv, const float* __restrict__ bbv,
                        int layer) {
    const int ch  = blockIdx.x;
    const int by  = blockIdx.y;          // b*2 + dir
    const int b   = by >> 1, dir = by & 1;
    const int h   = threadIdx.x;
    const float bf = ((dir == 0 ? bfv : bbv) + layer * 2 * Hc)[h];
    const float* base = g_U + ((ch * CHS) * Bc + b) * NJ + dir * 512 + h;

    float c = 0.0f, P = 1.0f;
#pragma unroll 4
    for (int s = 0; s < CHS; s++) {
        const float* u = base + s * (Bc * NJ);
        float u0 = u[0];
        float uf = u[128];
        float f = sig_fast(uf + bf);
        c = u0 + f * (c - u0);
        P *= f;
    }
    const int idx = (ch * 32 + by) * Hc + h;
    g_cend[idx] = c;
    g_P[idx]    = P;
}

__global__ void k_scanB() {
    const int by = blockIdx.x;
    const int h  = threadIdx.x;
    float cin = 0.0f;
#pragma unroll
    for (int ch = 0; ch < NCH; ch++) {
        const int idx = (ch * 32 + by) * Hc + h;
        g_cin[idx] = cin;
        cin = g_P[idx] * cin + g_cend[idx];
    }
}

__global__ void k_scanC(const float* __restrict__ bfv, const float* __restrict__ bbv,
                        int layer, int is_last, float* __restrict__ out_final) {
    const int ch  = blockIdx.x;
    const int by  = blockIdx.y;
    const int b   = by >> 1, dir = by & 1;
    const int h   = threadIdx.x;
    const float* bias = (dir == 0 ? bfv : bbv) + layer * 2 * Hc;
    const float bf = bias[h];
    const float br = bias[Hc + h];
    const float* base = g_U + ((ch * CHS) * Bc + b) * NJ + dir * 512 + h;

    float c = g_cin[(ch * 32 + by) * Hc + h];
#pragma unroll 4
    for (int s = 0; s < CHS; s++) {
        const float* u = base + s * (Bc * NJ);
        float u0 = u[0];
        float uf = u[128];
        float ur = u[256];
        float hw = u[384];
        float f = sig_fast(uf + bf);
        float r = sig_fast(ur + br);
        c = u0 + f * (c - u0);
        float hv = hw + r * (tanh_fast(c) - hw);
        const int s_abs = ch * CHS + s;
        if (is_last)
            out_final[b * (Sc * Dc) + s_abs * Dc + dir * Hc + h] = hv;
        else
            g_out[(s_abs * Bc + b) * Dc + dir * Hc + h] = hv;
    }
}

// ---------------------------------------------------------------------------
extern "C" void kernel_launch(void* const* d_in, const int* in_sizes, int n_in,
                              void* d_out, int out_size) {
    const float* x            = (const float*)d_in[0];
    const unsigned char* mask = (const unsigned char*)d_in[1];
    const int* act            = (const int*)d_in[2];
    const float* w1           = (const float*)d_in[3];
    const float* b1           = (const float*)d_in[4];
    const float* w2           = (const float*)d_in[5];
    const float* b2           = (const float*)d_in[6];
    const float* v            = (const float*)d_in[7];
    const float* swf          = (const float*)d_in[8];
    const float* sbf          = (const float*)d_in[9];
    const float* swb          = (const float*)d_in[10];
    const float* sbb          = (const float*)d_in[11];
    float* out = (float*)d_out;

    k_xt<<<dim3(Bc, 4), 256>>>(x, w1, b1, act);

    for (int layer = 0; layer < 2; layer++) {
        k_attn<<<dim3(Sc / GRP, Bc), 256>>>(x, layer == 0 ? 1 : 0, mask, act, w2, b2, v);
        k_sru_gemm<<<dim3(32, 16), 256>>>(swf, swb, layer);
        k_scanA<<<dim3(NCH, 32), Hc>>>(sbf, sbb, layer);
        k_scanB<<<32, Hc>>>();
        k_scanC<<<dim3(NCH, 32), Hc>>>(sbf, sbb, layer, layer == 1 ? 1 : 0, out);
    }
}

// round 4
// speedup vs baseline: 2.1633x; 1.5227x over previous
#include <cuda_runtime.h>
#include <cuda_bf16.h>
#include <math.h>
#include <stdint.h>

#define Bc   16
#define Sc   256
#define Dc   256
#define Hc   128
#define DKc  64
#define NIN  512
#define NJ   1024
#define GRP  8
#define NCH  16
#define CHS  16

// GEMM config: BM=BN=128, BK=32, 3 cp.async stages, 3 bf16-split passes.
#define NIT    48            // 3 passes x 16 K-chunks of 32
#define STG_A  8192          // 128 x 32 bf16
#define STG_B  8192
#define STAGE  16384
// NOTE: 3 stages x 16KB = 48KB static smem (at the static limit).

// ---------------- scratch -----------------
__device__ float g_xtT[Bc * DKc * Sc];
__device__ float g_out[Sc * Bc * Dc];
__device__ float g_U[Sc * Bc * NJ];
__device__ float g_cend[NCH * 32 * Hc];
__device__ float g_P[NCH * 32 * Hc];
__device__ float g_cin[NCH * 32 * Hc];
__device__ __align__(256) __nv_bfloat16 g_Ahi[Sc * Bc * NIN];
__device__ __align__(256) __nv_bfloat16 g_Alo[Sc * Bc * NIN];
__device__ __align__(256) __nv_bfloat16 g_Whi[2 * NJ * NIN];   // [layer][n][k]
__device__ __align__(256) __nv_bfloat16 g_Wlo[2 * NJ * NIN];

// ---------------- helpers -----------------
__device__ __forceinline__ float tanh_fast(float x) {
    float y; asm("tanh.approx.f32 %0, %1;" : "=f"(y) : "f"(x)); return y;
}
__device__ __forceinline__ float sig_fast(float x) {
    float e, r;
    asm("ex2.approx.f32 %0, %1;" : "=f"(e) : "f"(x * -1.4426950408889634f));
    asm("rcp.approx.f32 %0, %1;" : "=f"(r) : "f"(1.0f + e));
    return r;
}
__device__ __forceinline__ uint32_t smem_u32(const void* p) {
    uint32_t a;
    asm("{ .reg .u64 t; cvta.to.shared.u64 t, %1; cvt.u32.u64 %0, t; }" : "=r"(a) : "l"(p));
    return a;
}
__device__ __forceinline__ void cp16(uint32_t d, const void* s) {
    asm volatile("cp.async.cg.shared.global [%0], [%1], 16;\n" :: "r"(d), "l"(s));
}
#define CP_COMMIT() asm volatile("cp.async.commit_group;\n" ::: "memory")
#define CP_WAIT2()  asm volatile("cp.async.wait_group 2;\n" ::: "memory")

__device__ __forceinline__ void ldsm4(uint32_t* r, uint32_t addr) {
    asm volatile("ldmatrix.sync.aligned.m8n8.x4.shared.b16 {%0,%1,%2,%3}, [%4];"
                 : "=r"(r[0]), "=r"(r[1]), "=r"(r[2]), "=r"(r[3]) : "r"(addr));
}
__device__ __forceinline__ void mma16816(float* c, const uint32_t* a, const uint32_t* b) {
    asm volatile("mma.sync.aligned.m16n8k16.row.col.f32.bf16.bf16.f32 "
                 "{%0,%1,%2,%3}, {%4,%5,%6,%7}, {%8,%9}, {%0,%1,%2,%3};"
                 : "+f"(c[0]), "+f"(c[1]), "+f"(c[2]), "+f"(c[3])
                 : "r"(a[0]), "r"(a[1]), "r"(a[2]), "r"(a[3]), "r"(b[0]), "r"(b[1]));
}

// ---------------------------------------------------------------------------
// weight convert+transpose: g_W{hi,lo}[(l*1024+n)*512+k] from Wf/Wb [l][k][n]
// ---------------------------------------------------------------------------
__global__ void k_wconv(const float* __restrict__ wf, const float* __restrict__ wb) {
    const int k0 = blockIdx.x * 32, nt = blockIdx.y * 32, l = blockIdx.z;
    const float* W = (nt < 512) ? (wf + l * 262144 + nt) : (wb + l * 262144 + (nt - 512));
    __shared__ float t[32][33];
    const int tx = threadIdx.x, ty = threadIdx.y;
    for (int i = ty; i < 32; i += 8)
        t[i][tx] = W[(k0 + i) * 512 + tx];
    __syncthreads();
    for (int i = ty; i < 32; i += 8) {
        float v = t[tx][i];
        __nv_bfloat16 hi = __float2bfloat16(v);
        __nv_bfloat16 lo = __float2bfloat16(v - __bfloat162float(hi));
        size_t idx = (size_t)(l * NJ + nt + i) * NIN + k0 + tx;
        g_Whi[idx] = hi;
        g_Wlo[idx] = lo;
    }
}

// ---------------------------------------------------------------------------
// xtT[b][k][l] = b1[a,k] + sum_d x[b,l,d]*w1[a,d,k]  (once)
// ---------------------------------------------------------------------------
__global__ void k_xt(const float* __restrict__ x, const float* __restrict__ w1,
                     const float* __restrict__ b1, const int* __restrict__ act) {
    const int b = blockIdx.x, lt = blockIdx.y;
    const int a = act[b];
    const float* xb = x + b * Sc * Dc + lt * 64 * Dc;
    const float* wa = w1 + a * Dc * DKc;
    __shared__ float xs[32][65];
    __shared__ float ws[32][64];
    const int tid = threadIdx.x;
    const int ty = tid >> 4, tx = tid & 15;
    float acc[4][4] = {};
    for (int d0 = 0; d0 < Dc; d0 += 32) {
        for (int i = tid; i < 64 * 32; i += 256) {
            int l = i >> 5, d = i & 31;
            xs[d][l] = xb[l * Dc + d0 + d];
        }
        for (int i = tid; i < 32 * 64; i += 256) {
            int d = i >> 6, k = i & 63;
            ws[d][k] = wa[(d0 + d) * DKc + k];
        }
        __syncthreads();
#pragma unroll
        for (int d = 0; d < 32; d++) {
            float af[4], bfv[4];
#pragma unroll
            for (int i = 0; i < 4; i++) af[i] = xs[d][ty * 4 + i];
#pragma unroll
            for (int j = 0; j < 4; j++) bfv[j] = ws[d][tx * 4 + j];
#pragma unroll
            for (int i = 0; i < 4; i++)
#pragma unroll
                for (int j = 0; j < 4; j++) acc[i][j] = fmaf(af[i], bfv[j], acc[i][j]);
        }
        __syncthreads();
    }
#pragma unroll
    for (int j = 0; j < 4; j++) {
        int k = tx * 4 + j;
        float bb = b1[a * DKc + k];
#pragma unroll
        for (int i = 0; i < 4; i++) {
            int l = lt * 64 + ty * 4 + i;
            g_xtT[b * (DKc * Sc) + k * Sc + l] = acc[i][j] + bb;
        }
    }
}

// ---------------------------------------------------------------------------
// Attention: writes cat(out,pools) rows as bf16 hi/lo (GEMM A operand).
// ---------------------------------------------------------------------------
__global__ void k_attn(const float* __restrict__ x, int layer0,
                       const unsigned char* __restrict__ mask,
                       const int* __restrict__ act,
                       const float* __restrict__ w2, const float* __restrict__ b2,
                       const float* __restrict__ v) {
    const int s0 = blockIdx.x * GRP;
    const int b = blockIdx.y;
    const int a = act[b];
    const int tid = threadIdx.x;

    __shared__ float row[GRP][Dc];
    __shared__ float yt[GRP][DKc];
    __shared__ float vv[DKc];
    __shared__ __align__(16) float att[Sc][GRP];
    __shared__ float ytp[GRP][4][DKc];
    __shared__ float red[8][GRP];
    __shared__ float gmax[GRP], ginv[GRP];

#pragma unroll
    for (int g = 0; g < GRP; g++) {
        int s = s0 + g;
        float val = layer0 ? x[b * Sc * Dc + s * Dc + tid]
                           : g_out[(s * Bc + b) * Dc + tid];
        row[g][tid] = val;
        __nv_bfloat16 hi = __float2bfloat16(val);
        size_t idx = (size_t)(s * Bc + b) * NIN + tid;
        g_Ahi[idx] = hi;
        g_Alo[idx] = __float2bfloat16(val - __bfloat162float(hi));
    }
    if (tid < DKc) vv[tid] = v[a * DKc + tid];
    __syncthreads();

    {
        const float* wa = w2 + a * Dc * DKc;
        const int k = tid & 63, part = tid >> 6;
        float acc[GRP] = {};
        for (int i = 0; i < 64; i++) {
            int d = part * 64 + i;
            float w = wa[d * DKc + k];
#pragma unroll
            for (int g = 0; g < GRP; g++) acc[g] = fmaf(row[g][d], w, acc[g]);
        }
#pragma unroll
        for (int g = 0; g < GRP; g++) ytp[g][part][k] = acc[g];
    }
    __syncthreads();
    for (int idx = tid; idx < GRP * DKc; idx += 256) {
        int g = idx >> 6, k = idx & 63;
        yt[g][k] = ytp[g][0][k] + ytp[g][1][k] + ytp[g][2][k] + ytp[g][3][k]
                 + b2[a * DKc + k];
    }
    __syncthreads();

    float sc[GRP] = {};
    {
        const float* xt = g_xtT + b * (DKc * Sc);
#pragma unroll 4
        for (int k = 0; k < DKc; k++) {
            float xv = xt[k * Sc + tid];
            float vk = vv[k];
#pragma unroll
            for (int g = 0; g < GRP; g++)
                sc[g] = fmaf(vk, tanh_fast(xv + yt[g][k]), sc[g]);
        }
        if (mask[b * Sc + tid]) {
#pragma unroll
            for (int g = 0; g < GRP; g++) sc[g] = -1e30f;
        }
    }

    const int lane = tid & 31, wid = tid >> 5;
#pragma unroll
    for (int g = 0; g < GRP; g++) {
        float m = sc[g];
#pragma unroll
        for (int o = 16; o > 0; o >>= 1) m = fmaxf(m, __shfl_xor_sync(0xffffffffu, m, o));
        if (lane == 0) red[wid][g] = m;
    }
    __syncthreads();
    if (tid < GRP) {
        float m = red[0][tid];
#pragma unroll
        for (int w = 1; w < 8; w++) m = fmaxf(m, red[w][tid]);
        gmax[tid] = m;
    }
    __syncthreads();
    float ex[GRP];
#pragma unroll
    for (int g = 0; g < GRP; g++) {
        ex[g] = __expf(sc[g] - gmax[g]);
        att[tid][g] = ex[g];
    }
#pragma unroll
    for (int g = 0; g < GRP; g++) {
        float s = ex[g];
#pragma unroll
        for (int o = 16; o > 0; o >>= 1) s += __shfl_xor_sync(0xffffffffu, s, o);
        if (lane == 0) red[wid][g] = s;
    }
    __syncthreads();
    if (tid < GRP) {
        float s = red[0][tid];
#pragma unroll
        for (int w = 1; w < 8; w++) s += red[w][tid];
        ginv[tid] = 1.0f / s;
    }
    __syncthreads();

    float p[GRP] = {};
    const float* xb = x + b * Sc * Dc;
#pragma unroll 2
    for (int l = 0; l < Sc; l++) {
        float xv = xb[l * Dc + tid];
        float4 a0 = *reinterpret_cast<const float4*>(&att[l][0]);
        float4 a1 = *reinterpret_cast<const float4*>(&att[l][4]);
        p[0] = fmaf(a0.x, xv, p[0]); p[1] = fmaf(a0.y, xv, p[1]);
        p[2] = fmaf(a0.z, xv, p[2]); p[3] = fmaf(a0.w, xv, p[3]);
        p[4] = fmaf(a1.x, xv, p[4]); p[5] = fmaf(a1.y, xv, p[5]);
        p[6] = fmaf(a1.z, xv, p[6]); p[7] = fmaf(a1.w, xv, p[7]);
    }
#pragma unroll
    for (int g = 0; g < GRP; g++) {
        int s = s0 + g;
        float val = p[g] * ginv[g];
        __nv_bfloat16 hi = __float2bfloat16(val);
        size_t idx = (size_t)(s * Bc + b) * NIN + Dc + tid;
        g_Ahi[idx] = hi;
        g_Alo[idx] = __float2bfloat16(val - __bfloat162float(hi));
    }
}

// ---------------------------------------------------------------------------
// HMMA GEMM: U[4096,1024] = (Ahi+Alo) @ (Whi+Wlo)^T  (drop lo*lo)
// grid (32, 8): 128x128 fp32 tile, fp32 accum in regs across all 3 passes.
// BK=32, 3-stage cp.async pipeline, 48KB static smem, XOR-16B swizzle.
// ---------------------------------------------------------------------------
__device__ __forceinline__ void g_load(int c, int tid, uint32_t sb,
                                       int mt, int nt, int layer) {
    const int pass = c >> 4, kc = (c & 15) << 5;
    const __nv_bfloat16* Ap = (pass == 2 ? g_Alo : g_Ahi)
                              + (size_t)(mt * 128) * NIN + kc;
    const __nv_bfloat16* Bp = (pass == 1 ? g_Wlo : g_Whi)
                              + (size_t)(layer * NJ + nt * 128) * NIN + kc;
    const uint32_t ab = sb + (c % 3) * STAGE;
    const uint32_t bb = ab + STG_A;
#pragma unroll
    for (int i = 0; i < 2; i++) {
        int vi = tid + i * 256, r = vi >> 2, ch = vi & 3;
        cp16(ab + r * 64 + ((ch ^ (r & 3)) << 4), Ap + (size_t)r * NIN + ch * 8);
    }
#pragma unroll
    for (int i = 0; i < 2; i++) {
        int vi = tid + i * 256, r = vi >> 2, ch = vi & 3;
        cp16(bb + r * 64 + ((ch ^ (r & 3)) << 4), Bp + (size_t)r * NIN + ch * 8);
    }
}

__global__ void __launch_bounds__(256) k_wgemm(int layer) {
    __shared__ __align__(128) char sm[3 * STAGE];
    const uint32_t sb = smem_u32(sm);
    const int tid = threadIdx.x, wid = tid >> 5, lane = tid & 31;
    const int mt = blockIdx.x, nt = blockIdx.y;
    const int wm = wid & 3, wn = wid >> 2;

    float acc[2][8][4] = {};

    g_load(0, tid, sb, mt, nt, layer); CP_COMMIT();
    g_load(1, tid, sb, mt, nt, layer); CP_COMMIT();

    // per-thread ldmatrix row indices
    const int arow_b = wm * 32 + (lane & 15);       // + mtile*16
    const int brow_b = wn * 64 + (lane & 15);       // + npair*16
    const int khalf = lane >> 4;                    // 0/1 -> +8 in k

    for (int c = 0; c < NIT; c++) {
        if (c + 2 < NIT) g_load(c + 2, tid, sb, mt, nt, layer);
        CP_COMMIT();
        CP_WAIT2();
        __syncthreads();

        const uint32_t ab = sb + (c % 3) * STAGE;
        const uint32_t bb = ab + STG_A;
#pragma unroll
        for (int ks = 0; ks < 2; ks++) {
            const int k8 = ks * 2 + khalf;          // 16B chunk idx (0..3)
            uint32_t a[2][4], b[8][2];
#pragma unroll
            for (int mtile = 0; mtile < 2; mtile++) {
                int r = arow_b + mtile * 16;
                ldsm4(a[mtile], ab + r * 64 + ((k8 ^ (r & 3)) << 4));
            }
#pragma unroll
            for (int np = 0; np < 4; np++) {
                int r = brow_b + np * 16;
                uint32_t t[4];
                ldsm4(t, bb + r * 64 + ((k8 ^ (r & 3)) << 4));
                b[np * 2][0] = t[0]; b[np * 2 + 1][0] = t[1];
                b[np * 2][1] = t[2]; b[np * 2 + 1][1] = t[3];
            }
#pragma unroll
            for (int mtile = 0; mtile < 2; mtile++)
#pragma unroll
                for (int ntile = 0; ntile < 8; ntile++)
                    mma16816(acc[mtile][ntile], a[mtile], b[ntile]);
        }
        __syncthreads();
    }

    // epilogue: fp32 frags -> g_U
    const int m_b = mt * 128 + wm * 32 + (lane >> 2);
    const int n_b = nt * 128 + wn * 64 + (lane & 3) * 2;
#pragma unroll
    for (int mtile = 0; mtile < 2; mtile++) {
#pragma unroll
        for (int ntile = 0; ntile < 8; ntile++) {
            float* dst = g_U + (size_t)(m_b + mtile * 16) * NJ + n_b + ntile * 8;
            *reinterpret_cast<float2*>(dst) =
                make_float2(acc[mtile][ntile][0], acc[mtile][ntile][1]);
            *reinterpret_cast<float2*>(dst + 8 * NJ) =
                make_float2(acc[mtile][ntile][2], acc[mtile][ntile][3]);
        }
    }
}

// ---------------------------------------------------------------------------
// SRU chunked-parallel scan
// ---------------------------------------------------------------------------
__global__ void k_scanA(const float* __restrict__ bfv, const float* __restrict__ bbv,
                        int layer) {
    const int ch = blockIdx.x, by = blockIdx.y;
    const int b = by >> 1, dir = by & 1;
    const int h = threadIdx.x;
    const float bf = ((dir == 0 ? bfv : bbv) + layer * 2 * Hc)[h];
    const float* base = g_U + ((size_t)(ch * CHS) * Bc + b) * NJ + dir * 512 + h;
    float c = 0.0f, P = 1.0f;
#pragma unroll 4
    for (int s = 0; s < CHS; s++) {
        const float* u = base + (size_t)s * (Bc * NJ);
        float u0 = u[0], uf = u[128];
        float f = sig_fast(uf + bf);
        c = u0 + f * (c - u0);
        P *= f;
    }
    const int idx = (ch * 32 + by) * Hc + h;
    g_cend[idx] = c;
    g_P[idx] = P;
}

__global__ void k_scanB() {
    const int by = blockIdx.x;
    const int h = threadIdx.x;
    float cin = 0.0f;
#pragma unroll
    for (int ch = 0; ch < NCH; ch++) {
        const int idx = (ch * 32 + by) * Hc + h;
        g_cin[idx] = cin;
        cin = g_P[idx] * cin + g_cend[idx];
    }
}

__global__ void k_scanC(const float* __restrict__ bfv, const float* __restrict__ bbv,
                        int layer, int is_last, float* __restrict__ out_final) {
    const int ch = blockIdx.x, by = blockIdx.y;
    const int b = by >> 1, dir = by & 1;
    const int h = threadIdx.x;
    const float* bias = (dir == 0 ? bfv : bbv) + layer * 2 * Hc;
    const float bf = bias[h];
    const float br = bias[Hc + h];
    const float* base = g_U + ((size_t)(ch * CHS) * Bc + b) * NJ + dir * 512 + h;
    float c = g_cin[(ch * 32 + by) * Hc + h];
#pragma unroll 4
    for (int s = 0; s < CHS; s++) {
        const float* u = base + (size_t)s * (Bc * NJ);
        float u0 = u[0], uf = u[128], ur = u[256], hw = u[384];
        float f = sig_fast(uf + bf);
        float r = sig_fast(ur + br);
        c = u0 + f * (c - u0);
        float hv = hw + r * (tanh_fast(c) - hw);
        const int s_abs = ch * CHS + s;
        if (is_last)
            out_final[b * (Sc * Dc) + s_abs * Dc + dir * Hc + h] = hv;
        else
            g_out[(s_abs * Bc + b) * Dc + dir * Hc + h] = hv;
    }
}

// ---------------------------------------------------------------------------
extern "C" void kernel_launch(void* const* d_in, const int* in_sizes, int n_in,
                              void* d_out, int out_size) {
    const float* x            = (const float*)d_in[0];
    const unsigned char* mask = (const unsigned char*)d_in[1];
    const int* act            = (const int*)d_in[2];
    const float* w1           = (const float*)d_in[3];
    const float* b1           = (const float*)d_in[4];
    const float* w2           = (const float*)d_in[5];
    const float* b2           = (const float*)d_in[6];
    const float* v            = (const float*)d_in[7];
    const float* swf          = (const float*)d_in[8];
    const float* sbf          = (const float*)d_in[9];
    const float* swb          = (const float*)d_in[10];
    const float* sbb          = (const float*)d_in[11];
    float* out = (float*)d_out;

    k_wconv<<<dim3(16, 32, 2), dim3(32, 8)>>>(swf, swb);
    k_xt<<<dim3(Bc, 4), 256>>>(x, w1, b1, act);

    for (int layer = 0; layer < 2; layer++) {
        k_attn<<<dim3(Sc / GRP, Bc), 256>>>(x, layer == 0 ? 1 : 0, mask, act, w2, b2, v);
        k_wgemm<<<dim3(32, 8), 256>>>(layer);
        k_scanA<<<dim3(NCH, 32), Hc>>>(sbf, sbb, layer);
        k_scanB<<<32, Hc>>>();
        k_scanC<<<dim3(NCH, 32), Hc>>>(sbf, sbb, layer, layer == 1 ? 1 : 0, out);
    }
}

// round 5
// speedup vs baseline: 2.9076x; 1.3440x over previous
#include <cuda_runtime.h>
#include <cuda_fp16.h>
#include <math.h>
#include <stdint.h>

#define Bc   16
#define Sc   256
#define Dc   256
#define Hc   128
#define DKc  64
#define NIN  512
#define NJ   1024
#define GRP  8
#define NCH  16
#define CHS  16

// GEMM config: BM=BN=128, BK=32, 3 cp.async stages, single fp16 pass.
#define NIT    16            // 16 K-chunks of 32 (K=512)
#define STG_A  8192          // 128 x 32 fp16
#define STG_B  8192
#define STAGE  16384

// ---------------- scratch -----------------
__device__ float g_xtT[Bc * DKc * Sc];
__device__ float g_out[Sc * Bc * Dc];
__device__ float g_U[Sc * Bc * NJ];
__device__ float g_cend[NCH * 32 * Hc];
__device__ float g_P[NCH * 32 * Hc];
__device__ float g_cin[NCH * 32 * Hc];
__device__ __align__(256) __half g_Ah[Sc * Bc * NIN];
__device__ __align__(256) __half g_Wh[2 * NJ * NIN];   // [layer][n][k]

// ---------------- helpers -----------------
__device__ __forceinline__ float tanh_fast(float x) {
    float y; asm("tanh.approx.f32 %0, %1;" : "=f"(y) : "f"(x)); return y;
}
__device__ __forceinline__ float sig_fast(float x) {
    float e, r;
    asm("ex2.approx.f32 %0, %1;" : "=f"(e) : "f"(x * -1.4426950408889634f));
    asm("rcp.approx.f32 %0, %1;" : "=f"(r) : "f"(1.0f + e));
    return r;
}
__device__ __forceinline__ uint32_t smem_u32(const void* p) {
    uint32_t a;
    asm("{ .reg .u64 t; cvta.to.shared.u64 t, %1; cvt.u32.u64 %0, t; }" : "=r"(a) : "l"(p));
    return a;
}
__device__ __forceinline__ void cp16(uint32_t d, const void* s) {
    asm volatile("cp.async.cg.shared.global [%0], [%1], 16;\n" :: "r"(d), "l"(s));
}
#define CP_COMMIT() asm volatile("cp.async.commit_group;\n" ::: "memory")
#define CP_WAIT2()  asm volatile("cp.async.wait_group 2;\n" ::: "memory")

__device__ __forceinline__ void ldsm4(uint32_t* r, uint32_t addr) {
    asm volatile("ldmatrix.sync.aligned.m8n8.x4.shared.b16 {%0,%1,%2,%3}, [%4];"
                 : "=r"(r[0]), "=r"(r[1]), "=r"(r[2]), "=r"(r[3]) : "r"(addr));
}
__device__ __forceinline__ void mma16816(float* c, const uint32_t* a, const uint32_t* b) {
    asm volatile("mma.sync.aligned.m16n8k16.row.col.f32.f16.f16.f32 "
                 "{%0,%1,%2,%3}, {%4,%5,%6,%7}, {%8,%9}, {%0,%1,%2,%3};"
                 : "+f"(c[0]), "+f"(c[1]), "+f"(c[2]), "+f"(c[3])
                 : "r"(a[0]), "r"(a[1]), "r"(a[2]), "r"(a[3]), "r"(b[0]), "r"(b[1]));
}

// ---------------------------------------------------------------------------
// weight convert+transpose: g_Wh[(l*1024+n)*512+k] from Wf/Wb [l][k][n]
// ---------------------------------------------------------------------------
__global__ void k_wconv(const float* __restrict__ wf, const float* __restrict__ wb) {
    const int k0 = blockIdx.x * 32, nt = blockIdx.y * 32, l = blockIdx.z;
    const float* W = (nt < 512) ? (wf + l * 262144 + nt) : (wb + l * 262144 + (nt - 512));
    __shared__ float t[32][33];
    const int tx = threadIdx.x, ty = threadIdx.y;
    for (int i = ty; i < 32; i += 8)
        t[i][tx] = W[(k0 + i) * 512 + tx];
    __syncthreads();
    for (int i = ty; i < 32; i += 8) {
        size_t idx = (size_t)(l * NJ + nt + i) * NIN + k0 + tx;
        g_Wh[idx] = __float2half(t[tx][i]);
    }
}

// ---------------------------------------------------------------------------
// xtT[b][k][l] = b1[a,k] + sum_d x[b,l,d]*w1[a,d,k]  (once)
// ---------------------------------------------------------------------------
__global__ void k_xt(const float* __restrict__ x, const float* __restrict__ w1,
                     const float* __restrict__ b1, const int* __restrict__ act) {
    const int b = blockIdx.x, lt = blockIdx.y;
    const int a = act[b];
    const float* xb = x + b * Sc * Dc + lt * 64 * Dc;
    const float* wa = w1 + a * Dc * DKc;
    __shared__ float xs[32][65];
    __shared__ float ws[32][64];
    const int tid = threadIdx.x;
    const int ty = tid >> 4, tx = tid & 15;
    float acc[4][4] = {};
    for (int d0 = 0; d0 < Dc; d0 += 32) {
        for (int i = tid; i < 64 * 32; i += 256) {
            int l = i >> 5, d = i & 31;
            xs[d][l] = xb[l * Dc + d0 + d];
        }
        for (int i = tid; i < 32 * 64; i += 256) {
            int d = i >> 6, k = i & 63;
            ws[d][k] = wa[(d0 + d) * DKc + k];
        }
        __syncthreads();
#pragma unroll
        for (int d = 0; d < 32; d++) {
            float af[4], bfv[4];
#pragma unroll
            for (int i = 0; i < 4; i++) af[i] = xs[d][ty * 4 + i];
#pragma unroll
            for (int j = 0; j < 4; j++) bfv[j] = ws[d][tx * 4 + j];
#pragma unroll
            for (int i = 0; i < 4; i++)
#pragma unroll
                for (int j = 0; j < 4; j++) acc[i][j] = fmaf(af[i], bfv[j], acc[i][j]);
        }
        __syncthreads();
    }
#pragma unroll
    for (int j = 0; j < 4; j++) {
        int k = tx * 4 + j;
        float bb = b1[a * DKc + k];
#pragma unroll
        for (int i = 0; i < 4; i++) {
            int l = lt * 64 + ty * 4 + i;
            g_xtT[b * (DKc * Sc) + k * Sc + l] = acc[i][j] + bb;
        }
    }
}

// ---------------------------------------------------------------------------
// Attention: writes cat(out,pools) rows as fp16 (GEMM A operand).
// ---------------------------------------------------------------------------
__global__ void k_attn(const float* __restrict__ x, int layer0,
                       const unsigned char* __restrict__ mask,
                       const int* __restrict__ act,
                       const float* __restrict__ w2, const float* __restrict__ b2,
                       const float* __restrict__ v) {
    const int s0 = blockIdx.x * GRP;
    const int b = blockIdx.y;
    const int a = act[b];
    const int tid = threadIdx.x;

    __shared__ float row[GRP][Dc];
    __shared__ float yt[GRP][DKc];
    __shared__ float vv[DKc];
    __shared__ __align__(16) float att[Sc][GRP];
    __shared__ float ytp[GRP][4][DKc];
    __shared__ float red[8][GRP];
    __shared__ float gmax[GRP], ginv[GRP];

#pragma unroll
    for (int g = 0; g < GRP; g++) {
        int s = s0 + g;
        float val = layer0 ? x[b * Sc * Dc + s * Dc + tid]
                           : g_out[(s * Bc + b) * Dc + tid];
        row[g][tid] = val;
        g_Ah[(size_t)(s * Bc + b) * NIN + tid] = __float2half(val);
    }
    if (tid < DKc) vv[tid] = v[a * DKc + tid];
    __syncthreads();

    {
        const float* wa = w2 + a * Dc * DKc;
        const int k = tid & 63, part = tid >> 6;
        float acc[GRP] = {};
        for (int i = 0; i < 64; i++) {
            int d = part * 64 + i;
            float w = wa[d * DKc + k];
#pragma unroll
            for (int g = 0; g < GRP; g++) acc[g] = fmaf(row[g][d], w, acc[g]);
        }
#pragma unroll
        for (int g = 0; g < GRP; g++) ytp[g][part][k] = acc[g];
    }
    __syncthreads();
    for (int idx = tid; idx < GRP * DKc; idx += 256) {
        int g = idx >> 6, k = idx & 63;
        yt[g][k] = ytp[g][0][k] + ytp[g][1][k] + ytp[g][2][k] + ytp[g][3][k]
                 + b2[a * DKc + k];
    }
    __syncthreads();

    float sc[GRP] = {};
    {
        const float* xt = g_xtT + b * (DKc * Sc);
#pragma unroll 4
        for (int k = 0; k < DKc; k++) {
            float xv = xt[k * Sc + tid];
            float vk = vv[k];
#pragma unroll
            for (int g = 0; g < GRP; g++)
                sc[g] = fmaf(vk, tanh_fast(xv + yt[g][k]), sc[g]);
        }
        if (mask[b * Sc + tid]) {
#pragma unroll
            for (int g = 0; g < GRP; g++) sc[g] = -1e30f;
        }
    }

    const int lane = tid & 31, wid = tid >> 5;
#pragma unroll
    for (int g = 0; g < GRP; g++) {
        float m = sc[g];
#pragma unroll
        for (int o = 16; o > 0; o >>= 1) m = fmaxf(m, __shfl_xor_sync(0xffffffffu, m, o));
        if (lane == 0) red[wid][g] = m;
    }
    __syncthreads();
    if (tid < GRP) {
        float m = red[0][tid];
#pragma unroll
        for (int w = 1; w < 8; w++) m = fmaxf(m, red[w][tid]);
        gmax[tid] = m;
    }
    __syncthreads();
    float ex[GRP];
#pragma unroll
    for (int g = 0; g < GRP; g++) {
        ex[g] = __expf(sc[g] - gmax[g]);
        att[tid][g] = ex[g];
    }
#pragma unroll
    for (int g = 0; g < GRP; g++) {
        float s = ex[g];
#pragma unroll
        for (int o = 16; o > 0; o >>= 1) s += __shfl_xor_sync(0xffffffffu, s, o);
        if (lane == 0) red[wid][g] = s;
    }
    __syncthreads();
    if (tid < GRP) {
        float s = red[0][tid];
#pragma unroll
        for (int w = 1; w < 8; w++) s += red[w][tid];
        ginv[tid] = 1.0f / s;
    }
    __syncthreads();

    float p[GRP] = {};
    const float* xb = x + b * Sc * Dc;
#pragma unroll 2
    for (int l = 0; l < Sc; l++) {
        float xv = xb[l * Dc + tid];
        float4 a0 = *reinterpret_cast<const float4*>(&att[l][0]);
        float4 a1 = *reinterpret_cast<const float4*>(&att[l][4]);
        p[0] = fmaf(a0.x, xv, p[0]); p[1] = fmaf(a0.y, xv, p[1]);
        p[2] = fmaf(a0.z, xv, p[2]); p[3] = fmaf(a0.w, xv, p[3]);
        p[4] = fmaf(a1.x, xv, p[4]); p[5] = fmaf(a1.y, xv, p[5]);
        p[6] = fmaf(a1.z, xv, p[6]); p[7] = fmaf(a1.w, xv, p[7]);
    }
#pragma unroll
    for (int g = 0; g < GRP; g++) {
        int s = s0 + g;
        g_Ah[(size_t)(s * Bc + b) * NIN + Dc + tid] = __float2half(p[g] * ginv[g]);
    }
}

// ---------------------------------------------------------------------------
// HMMA GEMM: U[4096,1024] = Ah @ Wh^T  (fp16 in, fp32 accum)
// grid (32, 8): 128x128 fp32 tile. BK=32, 3-stage cp.async, XOR-16B swizzle.
// ---------------------------------------------------------------------------
__device__ __forceinline__ void g_load(int c, int tid, uint32_t sb,
                                       int mt, int nt, int layer) {
    const int kc = c << 5;
    const __half* Ap = g_Ah + (size_t)(mt * 128) * NIN + kc;
    const __half* Bp = g_Wh + (size_t)(layer * NJ + nt * 128) * NIN + kc;
    const uint32_t ab = sb + (c % 3) * STAGE;
    const uint32_t bb = ab + STG_A;
#pragma unroll
    for (int i = 0; i < 2; i++) {
        int vi = tid + i * 256, r = vi >> 2, ch = vi & 3;
        cp16(ab + r * 64 + ((ch ^ (r & 3)) << 4), Ap + (size_t)r * NIN + ch * 8);
    }
#pragma unroll
    for (int i = 0; i < 2; i++) {
        int vi = tid + i * 256, r = vi >> 2, ch = vi & 3;
        cp16(bb + r * 64 + ((ch ^ (r & 3)) << 4), Bp + (size_t)r * NIN + ch * 8);
    }
}

__global__ void __launch_bounds__(256) k_wgemm(int layer) {
    __shared__ __align__(128) char sm[3 * STAGE];
    const uint32_t sb = smem_u32(sm);
    const int tid = threadIdx.x, wid = tid >> 5, lane = tid & 31;
    const int mt = blockIdx.x, nt = blockIdx.y;
    const int wm = wid & 3, wn = wid >> 2;

    float acc[2][8][4] = {};

    g_load(0, tid, sb, mt, nt, layer); CP_COMMIT();
    g_load(1, tid, sb, mt, nt, layer); CP_COMMIT();

    const int arow_b = wm * 32 + (lane & 15);
    const int brow_b = wn * 64 + (lane & 15);
    const int khalf = lane >> 4;

    for (int c = 0; c < NIT; c++) {
        if (c + 2 < NIT) g_load(c + 2, tid, sb, mt, nt, layer);
        CP_COMMIT();
        CP_WAIT2();
        __syncthreads();

        const uint32_t ab = sb + (c % 3) * STAGE;
        const uint32_t bb = ab + STG_A;
#pragma unroll
        for (int ks = 0; ks < 2; ks++) {
            const int k8 = ks * 2 + khalf;
            uint32_t a[2][4], b[8][2];
#pragma unroll
            for (int mtile = 0; mtile < 2; mtile++) {
                int r = arow_b + mtile * 16;
                ldsm4(a[mtile], ab + r * 64 + ((k8 ^ (r & 3)) << 4));
            }
#pragma unroll
            for (int np = 0; np < 4; np++) {
                int r = brow_b + np * 16;
                uint32_t t[4];
                ldsm4(t, bb + r * 64 + ((k8 ^ (r & 3)) << 4));
                b[np * 2][0] = t[0]; b[np * 2 + 1][0] = t[1];
                b[np * 2][1] = t[2]; b[np * 2 + 1][1] = t[3];
            }
#pragma unroll
            for (int mtile = 0; mtile < 2; mtile++)
#pragma unroll
                for (int ntile = 0; ntile < 8; ntile++)
                    mma16816(acc[mtile][ntile], a[mtile], b[ntile]);
        }
        __syncthreads();
    }

    const int m_b = mt * 128 + wm * 32 + (lane >> 2);
    const int n_b = nt * 128 + wn * 64 + (lane & 3) * 2;
#pragma unroll
    for (int mtile = 0; mtile < 2; mtile++) {
#pragma unroll
        for (int ntile = 0; ntile < 8; ntile++) {
            float* dst = g_U + (size_t)(m_b + mtile * 16) * NJ + n_b + ntile * 8;
            *reinterpret_cast<float2*>(dst) =
                make_float2(acc[mtile][ntile][0], acc[mtile][ntile][1]);
            *reinterpret_cast<float2*>(dst + 8 * NJ) =
                make_float2(acc[mtile][ntile][2], acc[mtile][ntile][3]);
        }
    }
}

// ---------------------------------------------------------------------------
// SRU chunked-parallel scan
// ---------------------------------------------------------------------------
__global__ void k_scanA(const float* __restrict__ bfv, const float* __restrict__ bbv,
                        int layer) {
    const int ch = blockIdx.x, by = blockIdx.y;
    const int b = by >> 1, dir = by & 1;
    const int h = threadIdx.x;
    const float bf = ((dir == 0 ? bfv : bbv) + layer * 2 * Hc)[h];
    const float* base = g_U + ((size_t)(ch * CHS) * Bc + b) * NJ + dir * 512 + h;
    float c = 0.0f, P = 1.0f;
#pragma unroll 4
    for (int s = 0; s < CHS; s++) {
        const float* u = base + (size_t)s * (Bc * NJ);
        float u0 = u[0], uf = u[128];
        float f = sig_fast(uf + bf);
        c = u0 + f * (c - u0);
        P *= f;
    }
    const int idx = (ch * 32 + by) * Hc + h;
    g_cend[idx] = c;
    g_P[idx] = P;
}

__global__ void k_scanB() {
    const int by = blockIdx.x;
    const int h = threadIdx.x;
    float cin = 0.0f;
#pragma unroll
    for (int ch = 0; ch < NCH; ch++) {
        const int idx = (ch * 32 + by) * Hc + h;
        g_cin[idx] = cin;
        cin = g_P[idx] * cin + g_cend[idx];
    }
}

__global__ void k_scanC(const float* __restrict__ bfv, const float* __restrict__ bbv,
                        int layer, int is_last, float* __restrict__ out_final) {
    const int ch = blockIdx.x, by = blockIdx.y;
    const int b = by >> 1, dir = by & 1;
    const int h = threadIdx.x;
    const float* bias = (dir == 0 ? bfv : bbv) + layer * 2 * Hc;
    const float bf = bias[h];
    const float br = bias[Hc + h];
    const float* base = g_U + ((size_t)(ch * CHS) * Bc + b) * NJ + dir * 512 + h;
    float c = g_cin[(ch * 32 + by) * Hc + h];
#pragma unroll 4
    for (int s = 0; s < CHS; s++) {
        const float* u = base + (size_t)s * (Bc * NJ);
        float u0 = u[0], uf = u[128], ur = u[256], hw = u[384];
        float f = sig_fast(uf + bf);
        float r = sig_fast(ur + br);
        c = u0 + f * (c - u0);
        float hv = hw + r * (tanh_fast(c) - hw);
        const int s_abs = ch * CHS + s;
        if (is_last)
            out_final[b * (Sc * Dc) + s_abs * Dc + dir * Hc + h] = hv;
        else
            g_out[(s_abs * Bc + b) * Dc + dir * Hc + h] = hv;
    }
}

// ---------------------------------------------------------------------------
extern "C" void kernel_launch(void* const* d_in, const int* in_sizes, int n_in,
                              void* d_out, int out_size) {
    const float* x            = (const float*)d_in[0];
    const unsigned char* mask = (const unsigned char*)d_in[1];
    const int* act            = (const int*)d_in[2];
    const float* w1           = (const float*)d_in[3];
    const float* b1           = (const float*)d_in[4];
    const float* w2           = (const float*)d_in[5];
    const float* b2           = (const float*)d_in[6];
    const float* v            = (const float*)d_in[7];
    const float* swf          = (const float*)d_in[8];
    const float* sbf          = (const float*)d_in[9];
    const float* swb          = (const float*)d_in[10];
    const float* sbb          = (const float*)d_in[11];
    float* out = (float*)d_out;

    k_wconv<<<dim3(16, 32, 2), dim3(32, 8)>>>(swf, swb);
    k_xt<<<dim3(Bc, 4), 256>>>(x, w1, b1, act);

    for (int layer = 0; layer < 2; layer++) {
        k_attn<<<dim3(Sc / GRP, Bc), 256>>>(x, layer == 0 ? 1 : 0, mask, act, w2, b2, v);
        k_wgemm<<<dim3(32, 8), 256>>>(layer);
        k_scanA<<<dim3(NCH, 32), Hc>>>(sbf, sbb, layer);
        k_scanB<<<32, Hc>>>();
        k_scanC<<<dim3(NCH, 32), Hc>>>(sbf, sbb, layer, layer == 1 ? 1 : 0, out);
    }
}

// round 6
// speedup vs baseline: 3.3748x; 1.1607x over previous
#include <cuda_runtime.h>
#include <cuda_fp16.h>
#include <math.h>
#include <stdint.h>

#define Bc   16
#define Sc   256
#define Dc   256
#define Hc   128
#define DKc  64
#define NIN  512
#define NJ   1024
#define GRP  8
#define NCH  16
#define CHS  16

// GEMM config: BM=BN=128, BK=32, 3 cp.async stages, single fp16 pass.
#define NIT    16
#define STG_A  8192
#define STG_B  8192
#define STAGE  16384

// ---------------- scratch -----------------
__device__ float g_xtT[Bc * DKc * Sc];
__device__ float g_out[Sc * Bc * Dc];
__device__ float g_U[Sc * Bc * NJ];
__device__ float g_cend[NCH * 32 * Hc];
__device__ float g_P[NCH * 32 * Hc];
__device__ __align__(256) __half g_Ah[Sc * Bc * NIN];
__device__ __align__(256) __half g_Wh[2 * NJ * NIN];   // [layer][n][k]

// ---------------- helpers -----------------
__device__ __forceinline__ float tanh_fast(float x) {
    float y; asm("tanh.approx.f32 %0, %1;" : "=f"(y) : "f"(x)); return y;
}
__device__ __forceinline__ float sig_fast(float x) {
    float e, r;
    asm("ex2.approx.f32 %0, %1;" : "=f"(e) : "f"(x * -1.4426950408889634f));
    asm("rcp.approx.f32 %0, %1;" : "=f"(r) : "f"(1.0f + e));
    return r;
}
__device__ __forceinline__ uint32_t smem_u32(const void* p) {
    uint32_t a;
    asm("{ .reg .u64 t; cvta.to.shared.u64 t, %1; cvt.u32.u64 %0, t; }" : "=r"(a) : "l"(p));
    return a;
}
__device__ __forceinline__ void cp16(uint32_t d, const void* s) {
    asm volatile("cp.async.cg.shared.global [%0], [%1], 16;\n" :: "r"(d), "l"(s));
}
#define CP_COMMIT() asm volatile("cp.async.commit_group;\n" ::: "memory")
#define CP_WAIT2()  asm volatile("cp.async.wait_group 2;\n" ::: "memory")

__device__ __forceinline__ void ldsm4(uint32_t* r, uint32_t addr) {
    asm volatile("ldmatrix.sync.aligned.m8n8.x4.shared.b16 {%0,%1,%2,%3}, [%4];"
                 : "=r"(r[0]), "=r"(r[1]), "=r"(r[2]), "=r"(r[3]) : "r"(addr));
}
__device__ __forceinline__ void mma16816(float* c, const uint32_t* a, const uint32_t* b) {
    asm volatile("mma.sync.aligned.m16n8k16.row.col.f32.f16.f16.f32 "
                 "{%0,%1,%2,%3}, {%4,%5,%6,%7}, {%8,%9}, {%0,%1,%2,%3};"
                 : "+f"(c[0]), "+f"(c[1]), "+f"(c[2]), "+f"(c[3])
                 : "r"(a[0]), "r"(a[1]), "r"(a[2]), "r"(a[3]), "r"(b[0]), "r"(b[1]));
}

// ---------------------------------------------------------------------------
// weight convert+transpose: g_Wh[(l*1024+n)*512+k] from Wf/Wb [l][k][n]
// ---------------------------------------------------------------------------
__global__ void k_wconv(const float* __restrict__ wf, const float* __restrict__ wb) {
    const int k0 = blockIdx.x * 32, nt = blockIdx.y * 32, l = blockIdx.z;
    const float* W = (nt < 512) ? (wf + l * 262144 + nt) : (wb + l * 262144 + (nt - 512));
    __shared__ float t[32][33];
    const int tx = threadIdx.x, ty = threadIdx.y;
    for (int i = ty; i < 32; i += 8)
        t[i][tx] = W[(k0 + i) * 512 + tx];
    __syncthreads();
    for (int i = ty; i < 32; i += 8) {
        size_t idx = (size_t)(l * NJ + nt + i) * NIN + k0 + tx;
        g_Wh[idx] = __float2half(t[tx][i]);
    }
}

// ---------------------------------------------------------------------------
// xtT[b][k][l] = b1[a,k] + sum_d x[b,l,d]*w1[a,d,k]  (once)
// ---------------------------------------------------------------------------
__global__ void k_xt(const float* __restrict__ x, const float* __restrict__ w1,
                     const float* __restrict__ b1, const int* __restrict__ act) {
    const int b = blockIdx.x, lt = blockIdx.y;
    const int a = act[b];
    const float* xb = x + b * Sc * Dc + lt * 64 * Dc;
    const float* wa = w1 + a * Dc * DKc;
    __shared__ float xs[32][65];
    __shared__ float ws[32][64];
    const int tid = threadIdx.x;
    const int ty = tid >> 4, tx = tid & 15;
    float acc[4][4] = {};
    for (int d0 = 0; d0 < Dc; d0 += 32) {
        for (int i = tid; i < 64 * 32; i += 256) {
            int l = i >> 5, d = i & 31;
            xs[d][l] = xb[l * Dc + d0 + d];
        }
        for (int i = tid; i < 32 * 64; i += 256) {
            int d = i >> 6, k = i & 63;
            ws[d][k] = wa[(d0 + d) * DKc + k];
        }
        __syncthreads();
#pragma unroll
        for (int d = 0; d < 32; d++) {
            float af[4], bfv[4];
#pragma unroll
            for (int i = 0; i < 4; i++) af[i] = xs[d][ty * 4 + i];
#pragma unroll
            for (int j = 0; j < 4; j++) bfv[j] = ws[d][tx * 4 + j];
#pragma unroll
            for (int i = 0; i < 4; i++)
#pragma unroll
                for (int j = 0; j < 4; j++) acc[i][j] = fmaf(af[i], bfv[j], acc[i][j]);
        }
        __syncthreads();
    }
#pragma unroll
    for (int j = 0; j < 4; j++) {
        int k = tx * 4 + j;
        float bb = b1[a * DKc + k];
#pragma unroll
        for (int i = 0; i < 4; i++) {
            int l = lt * 64 + ty * 4 + i;
            g_xtT[b * (DKc * Sc) + k * Sc + l] = acc[i][j] + bb;
        }
    }
}

// ---------------------------------------------------------------------------
// Attention: no-max softmax (|score|<=8 provably), MLP-8 batched loads,
// yt stored [k][g] for float4 broadcast reads. Writes fp16 GEMM A rows.
// ---------------------------------------------------------------------------
__global__ void __launch_bounds__(256) k_attn(
        const float* __restrict__ x, int layer0,
        const unsigned char* __restrict__ mask,
        const int* __restrict__ act,
        const float* __restrict__ w2, const float* __restrict__ b2,
        const float* __restrict__ v) {
    const int s0 = blockIdx.x * GRP;
    const int b = blockIdx.y;
    const int a = act[b];
    const int tid = threadIdx.x;

    __shared__ float row[GRP][Dc];                 // 8KB
    __shared__ __align__(16) float yt2[DKc][GRP];  // [k][g] 2KB
    __shared__ float vv[DKc];
    __shared__ __align__(16) float att[Sc][GRP];   // 8KB
    __shared__ float ytp[4][GRP][DKc];             // 8KB
    __shared__ float red[8][GRP];
    __shared__ float ginv[GRP];

    const bool msk = mask[b * Sc + tid];

    // rows: batched loads, then smem + fp16 A writes
    {
        float rv[GRP];
#pragma unroll
        for (int g = 0; g < GRP; g++) {
            int s = s0 + g;
            rv[g] = layer0 ? x[b * Sc * Dc + s * Dc + tid]
                           : g_out[(s * Bc + b) * Dc + tid];
        }
#pragma unroll
        for (int g = 0; g < GRP; g++) {
            row[g][tid] = rv[g];
            g_Ah[(size_t)((s0 + g) * Bc + b) * NIN + tid] = __float2half(rv[g]);
        }
    }
    if (tid < DKc) vv[tid] = v[a * DKc + tid];
    __syncthreads();

    // yt partials: part = tid>>6 handles d in [part*64, part*64+64)
    {
        const float* wa = w2 + a * Dc * DKc;
        const int k = tid & 63, part = tid >> 6;
        float acc[GRP] = {};
        for (int i0 = 0; i0 < 64; i0 += 8) {
            float wv[8];
#pragma unroll
            for (int j = 0; j < 8; j++)
                wv[j] = wa[(part * 64 + i0 + j) * DKc + k];
#pragma unroll
            for (int j = 0; j < 8; j++) {
                int d = part * 64 + i0 + j;
#pragma unroll
                for (int g = 0; g < GRP; g++)
                    acc[g] = fmaf(row[g][d], wv[j], acc[g]);
            }
        }
#pragma unroll
        for (int g = 0; g < GRP; g++) ytp[part][g][k] = acc[g];
    }
    __syncthreads();
    for (int idx = tid; idx < GRP * DKc; idx += 256) {
        int g = idx >> 6, k = idx & 63;
        yt2[k][g] = ytp[0][g][k] + ytp[1][g][k] + ytp[2][g][k] + ytp[3][g][k]
                  + b2[a * DKc + k];
    }
    __syncthreads();

    // scores: thread = memory position l = tid, all 8 s rows
    float sc[GRP] = {};
    {
        const float* xt = g_xtT + b * (DKc * Sc);
        for (int k0 = 0; k0 < DKc; k0 += 8) {
            float xvv[8];
#pragma unroll
            for (int kk = 0; kk < 8; kk++)
                xvv[kk] = xt[(k0 + kk) * Sc + tid];
#pragma unroll
            for (int kk = 0; kk < 8; kk++) {
                const int k = k0 + kk;
                const float vk = vv[k];
                const float xv = xvv[kk];
                float4 y0 = *reinterpret_cast<const float4*>(&yt2[k][0]);
                float4 y1 = *reinterpret_cast<const float4*>(&yt2[k][4]);
                sc[0] = fmaf(vk, tanh_fast(xv + y0.x), sc[0]);
                sc[1] = fmaf(vk, tanh_fast(xv + y0.y), sc[1]);
                sc[2] = fmaf(vk, tanh_fast(xv + y0.z), sc[2]);
                sc[3] = fmaf(vk, tanh_fast(xv + y0.w), sc[3]);
                sc[4] = fmaf(vk, tanh_fast(xv + y1.x), sc[4]);
                sc[5] = fmaf(vk, tanh_fast(xv + y1.y), sc[5]);
                sc[6] = fmaf(vk, tanh_fast(xv + y1.z), sc[6]);
                sc[7] = fmaf(vk, tanh_fast(xv + y1.w), sc[7]);
            }
        }
    }

    // softmax without max-subtraction (scores bounded by sum|v| <= 8)
    const int lane = tid & 31, wid = tid >> 5;
    float ex[GRP];
#pragma unroll
    for (int g = 0; g < GRP; g++) {
        ex[g] = msk ? 0.0f : __expf(sc[g]);
        att[tid][g] = ex[g];
    }
#pragma unroll
    for (int g = 0; g < GRP; g++) {
        float s = ex[g];
#pragma unroll
        for (int o = 16; o > 0; o >>= 1) s += __shfl_xor_sync(0xffffffffu, s, o);
        if (lane == 0) red[wid][g] = s;
    }
    __syncthreads();
    if (tid < GRP) {
        float s = red[0][tid];
#pragma unroll
        for (int w = 1; w < 8; w++) s += red[w][tid];
        ginv[tid] = 1.0f / s;
    }
    __syncthreads();

    // pools: thread = feature d = tid, all 8 s rows; MLP-8 batched x loads
    float p[GRP] = {};
    {
        const float* xb = x + b * Sc * Dc;
        for (int l0 = 0; l0 < Sc; l0 += 8) {
            float xvv[8];
#pragma unroll
            for (int j = 0; j < 8; j++)
                xvv[j] = xb[(l0 + j) * Dc + tid];
#pragma unroll
            for (int j = 0; j < 8; j++) {
                float4 a0 = *reinterpret_cast<const float4*>(&att[l0 + j][0]);
                float4 a1 = *reinterpret_cast<const float4*>(&att[l0 + j][4]);
                const float xv = xvv[j];
                p[0] = fmaf(a0.x, xv, p[0]); p[1] = fmaf(a0.y, xv, p[1]);
                p[2] = fmaf(a0.z, xv, p[2]); p[3] = fmaf(a0.w, xv, p[3]);
                p[4] = fmaf(a1.x, xv, p[4]); p[5] = fmaf(a1.y, xv, p[5]);
                p[6] = fmaf(a1.z, xv, p[6]); p[7] = fmaf(a1.w, xv, p[7]);
            }
        }
    }
#pragma unroll
    for (int g = 0; g < GRP; g++) {
        int s = s0 + g;
        g_Ah[(size_t)(s * Bc + b) * NIN + Dc + tid] = __float2half(p[g] * ginv[g]);
    }
}

// ---------------------------------------------------------------------------
// HMMA GEMM: U[4096,1024] = Ah @ Wh^T  (fp16 in, fp32 accum) — unchanged
// ---------------------------------------------------------------------------
__device__ __forceinline__ void g_load(int c, int tid, uint32_t sb,
                                       int mt, int nt, int layer) {
    const int kc = c << 5;
    const __half* Ap = g_Ah + (size_t)(mt * 128) * NIN + kc;
    const __half* Bp = g_Wh + (size_t)(layer * NJ + nt * 128) * NIN + kc;
    const uint32_t ab = sb + (c % 3) * STAGE;
    const uint32_t bb = ab + STG_A;
#pragma unroll
    for (int i = 0; i < 2; i++) {
        int vi = tid + i * 256, r = vi >> 2, ch = vi & 3;
        cp16(ab + r * 64 + ((ch ^ (r & 3)) << 4), Ap + (size_t)r * NIN + ch * 8);
    }
#pragma unroll
    for (int i = 0; i < 2; i++) {
        int vi = tid + i * 256, r = vi >> 2, ch = vi & 3;
        cp16(bb + r * 64 + ((ch ^ (r & 3)) << 4), Bp + (size_t)r * NIN + ch * 8);
    }
}

__global__ void __launch_bounds__(256) k_wgemm(int layer) {
    __shared__ __align__(128) char sm[3 * STAGE];
    const uint32_t sb = smem_u32(sm);
    const int tid = threadIdx.x, wid = tid >> 5, lane = tid & 31;
    const int mt = blockIdx.x, nt = blockIdx.y;
    const int wm = wid & 3, wn = wid >> 2;

    float acc[2][8][4] = {};

    g_load(0, tid, sb, mt, nt, layer); CP_COMMIT();
    g_load(1, tid, sb, mt, nt, layer); CP_COMMIT();

    const int arow_b = wm * 32 + (lane & 15);
    const int brow_b = wn * 64 + (lane & 15);
    const int khalf = lane >> 4;

    for (int c = 0; c < NIT; c++) {
        if (c + 2 < NIT) g_load(c + 2, tid, sb, mt, nt, layer);
        CP_COMMIT();
        CP_WAIT2();
        __syncthreads();

        const uint32_t ab = sb + (c % 3) * STAGE;
        const uint32_t bb = ab + STG_A;
#pragma unroll
        for (int ks = 0; ks < 2; ks++) {
            const int k8 = ks * 2 + khalf;
            uint32_t a[2][4], b[8][2];
#pragma unroll
            for (int mtile = 0; mtile < 2; mtile++) {
                int r = arow_b + mtile * 16;
                ldsm4(a[mtile], ab + r * 64 + ((k8 ^ (r & 3)) << 4));
            }
#pragma unroll
            for (int np = 0; np < 4; np++) {
                int r = brow_b + np * 16;
                uint32_t t[4];
                ldsm4(t, bb + r * 64 + ((k8 ^ (r & 3)) << 4));
                b[np * 2][0] = t[0]; b[np * 2 + 1][0] = t[1];
                b[np * 2][1] = t[2]; b[np * 2 + 1][1] = t[3];
            }
#pragma unroll
            for (int mtile = 0; mtile < 2; mtile++)
#pragma unroll
                for (int ntile = 0; ntile < 8; ntile++)
                    mma16816(acc[mtile][ntile], a[mtile], b[ntile]);
        }
        __syncthreads();
    }

    const int m_b = mt * 128 + wm * 32 + (lane >> 2);
    const int n_b = nt * 128 + wn * 64 + (lane & 3) * 2;
#pragma unroll
    for (int mtile = 0; mtile < 2; mtile++) {
#pragma unroll
        for (int ntile = 0; ntile < 8; ntile++) {
            float* dst = g_U + (size_t)(m_b + mtile * 16) * NJ + n_b + ntile * 8;
            *reinterpret_cast<float2*>(dst) =
                make_float2(acc[mtile][ntile][0], acc[mtile][ntile][1]);
            *reinterpret_cast<float2*>(dst + 8 * NJ) =
                make_float2(acc[mtile][ntile][2], acc[mtile][ntile][3]);
        }
    }
}

// ---------------------------------------------------------------------------
// SRU chunked-parallel scan: pass A (chunk local), pass C (compose inline + emit)
// ---------------------------------------------------------------------------
__global__ void k_scanA(const float* __restrict__ bfv, const float* __restrict__ bbv,
                        int layer) {
    const int ch = blockIdx.x, by = blockIdx.y;
    const int b = by >> 1, dir = by & 1;
    const int h = threadIdx.x;
    const float bf = ((dir == 0 ? bfv : bbv) + layer * 2 * Hc)[h];
    const float* base = g_U + ((size_t)(ch * CHS) * Bc + b) * NJ + dir * 512 + h;
    float c = 0.0f, P = 1.0f;
#pragma unroll 4
    for (int s = 0; s < CHS; s++) {
        const float* u = base + (size_t)s * (Bc * NJ);
        float u0 = u[0], uf = u[128];
        float f = sig_fast(uf + bf);
        c = u0 + f * (c - u0);
        P *= f;
    }
    const int idx = (ch * 32 + by) * Hc + h;
    g_cend[idx] = c;
    g_P[idx] = P;
}

__global__ void k_scanC(const float* __restrict__ bfv, const float* __restrict__ bbv,
                        int layer, int is_last, float* __restrict__ out_final) {
    const int ch = blockIdx.x, by = blockIdx.y;
    const int b = by >> 1, dir = by & 1;
    const int h = threadIdx.x;
    const float* bias = (dir == 0 ? bfv : bbv) + layer * 2 * Hc;
    const float bf = bias[h];
    const float br = bias[Hc + h];
    const float* base = g_U + ((size_t)(ch * CHS) * Bc + b) * NJ + dir * 512 + h;

    // inline prefix compose over previous chunks (replaces scanB kernel)
    float c = 0.0f;
    for (int i = 0; i < ch; i++) {
        const int idx = (i * 32 + by) * Hc + h;
        c = g_P[idx] * c + g_cend[idx];
    }
#pragma unroll 4
    for (int s = 0; s < CHS; s++) {
        const float* u = base + (size_t)s * (Bc * NJ);
        float u0 = u[0], uf = u[128], ur = u[256], hw = u[384];
        float f = sig_fast(uf + bf);
        float r = sig_fast(ur + br);
        c = u0 + f * (c - u0);
        float hv = hw + r * (tanh_fast(c) - hw);
        const int s_abs = ch * CHS + s;
        if (is_last)
            out_final[b * (Sc * Dc) + s_abs * Dc + dir * Hc + h] = hv;
        else
            g_out[(s_abs * Bc + b) * Dc + dir * Hc + h] = hv;
    }
}

// ---------------------------------------------------------------------------
extern "C" void kernel_launch(void* const* d_in, const int* in_sizes, int n_in,
                              void* d_out, int out_size) {
    const float* x            = (const float*)d_in[0];
    const unsigned char* mask = (const unsigned char*)d_in[1];
    const int* act            = (const int*)d_in[2];
    const float* w1           = (const float*)d_in[3];
    const float* b1           = (const float*)d_in[4];
    const float* w2           = (const float*)d_in[5];
    const float* b2           = (const float*)d_in[6];
    const float* v            = (const float*)d_in[7];
    const float* swf          = (const float*)d_in[8];
    const float* sbf          = (const float*)d_in[9];
    const float* swb          = (const float*)d_in[10];
    const float* sbb          = (const float*)d_in[11];
    float* out = (float*)d_out;

    k_wconv<<<dim3(16, 32, 2), dim3(32, 8)>>>(swf, swb);
    k_xt<<<dim3(Bc, 4), 256>>>(x, w1, b1, act);

    for (int layer = 0; layer < 2; layer++) {
        k_attn<<<dim3(Sc / GRP, Bc), 256>>>(x, layer == 0 ? 1 : 0, mask, act, w2, b2, v);
        k_wgemm<<<dim3(32, 8), 256>>>(layer);
        k_scanA<<<dim3(NCH, 32), Hc>>>(sbf, sbb, layer);
        k_scanC<<<dim3(NCH, 32), Hc>>>(sbf, sbb, layer, layer == 1 ? 1 : 0, out);
    }
}

// round 7
// speedup vs baseline: 4.2390x; 1.2561x over previous
#include <cuda_runtime.h>
#include <cuda_fp16.h>
#include <math.h>
#include <stdint.h>

#define Bc   16
#define Sc   256
#define Dc   256
#define Hc   128
#define DKc  64
#define NIN  512
#define NJ   1024
#define GRP  8
#define NCH  16
#define CHS  16

// wgemm config
#define NIT    16
#define STG_A  8192
#define STG_B  8192
#define STAGE  16384
// pool-gemm config: A 64x32 fp16 (4KB) + B 32x128 fp16 (8KB)
#define PSTAGE 12288

// ---------------- scratch -----------------
__device__ float g_xtT[Bc * DKc * Sc];
__device__ float g_out[Sc * Bc * Dc];
__device__ float g_U[Sc * Bc * NJ];
__device__ float g_cend[NCH * 32 * Hc];
__device__ float g_P[NCH * 32 * Hc];
__device__ __align__(256) __half g_Ah[Sc * Bc * NIN];
__device__ __align__(256) __half g_Wh[2 * NJ * NIN];   // [layer][n][k]
__device__ __align__(256) __half g_att[Bc * Sc * Sc];  // [b][s][l] normalized
__device__ __align__(256) __half g_xh[Bc * Sc * Dc];   // x as fp16

// ---------------- helpers -----------------
__device__ __forceinline__ float tanh_fast(float x) {
    float y; asm("tanh.approx.f32 %0, %1;" : "=f"(y) : "f"(x)); return y;
}
__device__ __forceinline__ float sig_fast(float x) {
    float e, r;
    asm("ex2.approx.f32 %0, %1;" : "=f"(e) : "f"(x * -1.4426950408889634f));
    asm("rcp.approx.f32 %0, %1;" : "=f"(r) : "f"(1.0f + e));
    return r;
}
__device__ __forceinline__ uint32_t smem_u32(const void* p) {
    uint32_t a;
    asm("{ .reg .u64 t; cvta.to.shared.u64 t, %1; cvt.u32.u64 %0, t; }" : "=r"(a) : "l"(p));
    return a;
}
__device__ __forceinline__ void cp16(uint32_t d, const void* s) {
    asm volatile("cp.async.cg.shared.global [%0], [%1], 16;\n" :: "r"(d), "l"(s));
}
#define CP_COMMIT() asm volatile("cp.async.commit_group;\n" ::: "memory")
#define CP_WAIT2()  asm volatile("cp.async.wait_group 2;\n" ::: "memory")

__device__ __forceinline__ void ldsm4(uint32_t* r, uint32_t addr) {
    asm volatile("ldmatrix.sync.aligned.m8n8.x4.shared.b16 {%0,%1,%2,%3}, [%4];"
                 : "=r"(r[0]), "=r"(r[1]), "=r"(r[2]), "=r"(r[3]) : "r"(addr));
}
__device__ __forceinline__ void ldsm4t(uint32_t* r, uint32_t addr) {
    asm volatile("ldmatrix.sync.aligned.m8n8.x4.trans.shared.b16 {%0,%1,%2,%3}, [%4];"
                 : "=r"(r[0]), "=r"(r[1]), "=r"(r[2]), "=r"(r[3]) : "r"(addr));
}
__device__ __forceinline__ void mma16816(float* c, const uint32_t* a, const uint32_t* b) {
    asm volatile("mma.sync.aligned.m16n8k16.row.col.f32.f16.f16.f32 "
                 "{%0,%1,%2,%3}, {%4,%5,%6,%7}, {%8,%9}, {%0,%1,%2,%3};"
                 : "+f"(c[0]), "+f"(c[1]), "+f"(c[2]), "+f"(c[3])
                 : "r"(a[0]), "r"(a[1]), "r"(a[2]), "r"(a[3]), "r"(b[0]), "r"(b[1]));
}

// ---------------------------------------------------------------------------
// x -> fp16 copy (once; x is layer-invariant)
// ---------------------------------------------------------------------------
__global__ void k_xconv(const float* __restrict__ x) {
    int i = (blockIdx.x * 256 + threadIdx.x) * 4;
    float4 v = *reinterpret_cast<const float4*>(x + i);
    __half2 h0 = __floats2half2_rn(v.x, v.y);
    __half2 h1 = __floats2half2_rn(v.z, v.w);
    *reinterpret_cast<__half2*>(&g_xh[i])     = h0;
    *reinterpret_cast<__half2*>(&g_xh[i + 2]) = h1;
}

// ---------------------------------------------------------------------------
// weight convert+transpose: g_Wh[(l*1024+n)*512+k] from Wf/Wb [l][k][n]
// ---------------------------------------------------------------------------
__global__ void k_wconv(const float* __restrict__ wf, const float* __restrict__ wb) {
    const int k0 = blockIdx.x * 32, nt = blockIdx.y * 32, l = blockIdx.z;
    const float* W = (nt < 512) ? (wf + l * 262144 + nt) : (wb + l * 262144 + (nt - 512));
    __shared__ float t[32][33];
    const int tx = threadIdx.x, ty = threadIdx.y;
    for (int i = ty; i < 32; i += 8)
        t[i][tx] = W[(k0 + i) * 512 + tx];
    __syncthreads();
    for (int i = ty; i < 32; i += 8) {
        size_t idx = (size_t)(l * NJ + nt + i) * NIN + k0 + tx;
        g_Wh[idx] = __float2half(t[tx][i]);
    }
}

// ---------------------------------------------------------------------------
// xtT[b][k][l] = b1[a,k] + sum_d x[b,l,d]*w1[a,d,k]  (once)
// ---------------------------------------------------------------------------
__global__ void k_xt(const float* __restrict__ x, const float* __restrict__ w1,
                     const float* __restrict__ b1, const int* __restrict__ act) {
    const int b = blockIdx.x, lt = blockIdx.y;
    const int a = act[b];
    const float* xb = x + b * Sc * Dc + lt * 64 * Dc;
    const float* wa = w1 + a * Dc * DKc;
    __shared__ float xs[32][65];
    __shared__ float ws[32][64];
    const int tid = threadIdx.x;
    const int ty = tid >> 4, tx = tid & 15;
    float acc[4][4] = {};
    for (int d0 = 0; d0 < Dc; d0 += 32) {
        for (int i = tid; i < 64 * 32; i += 256) {
            int l = i >> 5, d = i & 31;
            xs[d][l] = xb[l * Dc + d0 + d];
        }
        for (int i = tid; i < 32 * 64; i += 256) {
            int d = i >> 6, k = i & 63;
            ws[d][k] = wa[(d0 + d) * DKc + k];
        }
        __syncthreads();
#pragma unroll
        for (int d = 0; d < 32; d++) {
            float af[4], bfv[4];
#pragma unroll
            for (int i = 0; i < 4; i++) af[i] = xs[d][ty * 4 + i];
#pragma unroll
            for (int j = 0; j < 4; j++) bfv[j] = ws[d][tx * 4 + j];
#pragma unroll
            for (int i = 0; i < 4; i++)
#pragma unroll
                for (int j = 0; j < 4; j++) acc[i][j] = fmaf(af[i], bfv[j], acc[i][j]);
        }
        __syncthreads();
    }
#pragma unroll
    for (int j = 0; j < 4; j++) {
        int k = tx * 4 + j;
        float bb = b1[a * DKc + k];
#pragma unroll
        for (int i = 0; i < 4; i++) {
            int l = lt * 64 + ty * 4 + i;
            g_xtT[b * (DKc * Sc) + k * Sc + l] = acc[i][j] + bb;
        }
    }
}

// ---------------------------------------------------------------------------
// Attention scores+softmax only: writes rnn-input rows (fp16) and the
// normalized attention matrix att[b][s][l] (fp16). Pools moved to k_pool.
// ---------------------------------------------------------------------------
__global__ void __launch_bounds__(256) k_attn(
        const float* __restrict__ x, int layer0,
        const unsigned char* __restrict__ mask,
        const int* __restrict__ act,
        const float* __restrict__ w2, const float* __restrict__ b2,
        const float* __restrict__ v) {
    const int s0 = blockIdx.x * GRP;
    const int b = blockIdx.y;
    const int a = act[b];
    const int tid = threadIdx.x;

    __shared__ float row[GRP][Dc];
    __shared__ __align__(16) float yt2[DKc][GRP];
    __shared__ float vv[DKc];
    __shared__ float ytp[4][GRP][DKc];
    __shared__ float red[8][GRP];
    __shared__ float ginv[GRP];

    const bool msk = mask[b * Sc + tid];

    {
        float rv[GRP];
#pragma unroll
        for (int g = 0; g < GRP; g++) {
            int s = s0 + g;
            rv[g] = layer0 ? x[b * Sc * Dc + s * Dc + tid]
                           : g_out[(s * Bc + b) * Dc + tid];
        }
#pragma unroll
        for (int g = 0; g < GRP; g++) {
            row[g][tid] = rv[g];
            g_Ah[(size_t)((s0 + g) * Bc + b) * NIN + tid] = __float2half(rv[g]);
        }
    }
    if (tid < DKc) vv[tid] = v[a * DKc + tid];
    __syncthreads();

    {
        const float* wa = w2 + a * Dc * DKc;
        const int k = tid & 63, part = tid >> 6;
        float acc[GRP] = {};
        for (int i0 = 0; i0 < 64; i0 += 8) {
            float wv[8];
#pragma unroll
            for (int j = 0; j < 8; j++)
                wv[j] = wa[(part * 64 + i0 + j) * DKc + k];
#pragma unroll
            for (int j = 0; j < 8; j++) {
                int d = part * 64 + i0 + j;
#pragma unroll
                for (int g = 0; g < GRP; g++)
                    acc[g] = fmaf(row[g][d], wv[j], acc[g]);
            }
        }
#pragma unroll
        for (int g = 0; g < GRP; g++) ytp[part][g][k] = acc[g];
    }
    __syncthreads();
    for (int idx = tid; idx < GRP * DKc; idx += 256) {
        int g = idx >> 6, k = idx & 63;
        yt2[k][g] = ytp[0][g][k] + ytp[1][g][k] + ytp[2][g][k] + ytp[3][g][k]
                  + b2[a * DKc + k];
    }
    __syncthreads();

    float sc[GRP] = {};
    {
        const float* xt = g_xtT + b * (DKc * Sc);
        for (int k0 = 0; k0 < DKc; k0 += 8) {
            float xvv[8];
#pragma unroll
            for (int kk = 0; kk < 8; kk++)
                xvv[kk] = xt[(k0 + kk) * Sc + tid];
#pragma unroll
            for (int kk = 0; kk < 8; kk++) {
                const int k = k0 + kk;
                const float vk = vv[k];
                const float xv = xvv[kk];
                float4 y0 = *reinterpret_cast<const float4*>(&yt2[k][0]);
                float4 y1 = *reinterpret_cast<const float4*>(&yt2[k][4]);
                sc[0] = fmaf(vk, tanh_fast(xv + y0.x), sc[0]);
                sc[1] = fmaf(vk, tanh_fast(xv + y0.y), sc[1]);
                sc[2] = fmaf(vk, tanh_fast(xv + y0.z), sc[2]);
                sc[3] = fmaf(vk, tanh_fast(xv + y0.w), sc[3]);
                sc[4] = fmaf(vk, tanh_fast(xv + y1.x), sc[4]);
                sc[5] = fmaf(vk, tanh_fast(xv + y1.y), sc[5]);
                sc[6] = fmaf(vk, tanh_fast(xv + y1.z), sc[6]);
                sc[7] = fmaf(vk, tanh_fast(xv + y1.w), sc[7]);
            }
        }
    }

    // softmax without max-subtraction (|score| <= sum|v| <= 8)
    const int lane = tid & 31, wid = tid >> 5;
    float ex[GRP];
#pragma unroll
    for (int g = 0; g < GRP; g++) ex[g] = msk ? 0.0f : __expf(sc[g]);
#pragma unroll
    for (int g = 0; g < GRP; g++) {
        float s = ex[g];
#pragma unroll
        for (int o = 16; o > 0; o >>= 1) s += __shfl_xor_sync(0xffffffffu, s, o);
        if (lane == 0) red[wid][g] = s;
    }
    __syncthreads();
    if (tid < GRP) {
        float s = red[0][tid];
#pragma unroll
        for (int w = 1; w < 8; w++) s += red[w][tid];
        ginv[tid] = 1.0f / s;
    }
    __syncthreads();

    // write normalized attention row (fp16, coalesced over l=tid)
#pragma unroll
    for (int g = 0; g < GRP; g++)
        g_att[((size_t)b * Sc + s0 + g) * Sc + tid] = __float2half(ex[g] * ginv[g]);
}

// ---------------------------------------------------------------------------
// Pools GEMM: pools[b][s][d] = sum_l att[b][s][l] * x[b][l][d]   (HMMA)
// grid (16 b, 4 stile, 2 ntile): M=64, N=128, K=256. A normal ldmatrix,
// B (x, [l][d] row-major) via ldmatrix.trans. Writes fp16 into g_Ah[...,256+d].
// ---------------------------------------------------------------------------
__device__ __forceinline__ void p_load(int c, int tid, uint32_t sb,
                                       int b, int st, int nt) {
    const int l0 = c << 5;
    const uint32_t ab = sb + (c % 3) * PSTAGE;
    const uint32_t bb = ab + 4096;
    // A: 64 s-rows x 32 l (64B rows), 256 cp16
    {
        int r = tid >> 2, ch = tid & 3;
        const __half* src = g_att + ((size_t)b * Sc + st * 64 + r) * Sc + l0 + ch * 8;
        cp16(ab + r * 64 + ((ch ^ (r & 3)) << 4), src);
    }
    // B: 32 l-rows x 128 d (256B rows), 512 cp16
#pragma unroll
    for (int i = 0; i < 2; i++) {
        int v = tid + i * 256, r = v >> 4, ch = v & 15;
        const __half* src = g_xh + ((size_t)b * Sc + l0 + r) * Dc + nt * 128 + ch * 8;
        cp16(bb + r * 256 + ((ch ^ (r & 15)) << 4), src);
    }
}

__global__ void __launch_bounds__(256) k_pool() {
    __shared__ __align__(128) char sm[3 * PSTAGE];
    const uint32_t sb = smem_u32(sm);
    const int tid = threadIdx.x, wid = tid >> 5, lane = tid & 31;
    const int b = blockIdx.x, st = blockIdx.y, nt = blockIdx.z;
    const int wm = wid & 1, wn = wid >> 1;   // 2 x 4 warps, 32x32 each

    float acc[2][4][4] = {};

    p_load(0, tid, sb, b, st, nt); CP_COMMIT();
    p_load(1, tid, sb, b, st, nt); CP_COMMIT();

    for (int c = 0; c < 8; c++) {
        if (c + 2 < 8) p_load(c + 2, tid, sb, b, st, nt);
        CP_COMMIT();
        CP_WAIT2();
        __syncthreads();

        const uint32_t ab = sb + (c % 3) * PSTAGE;
        const uint32_t bb = ab + 4096;
#pragma unroll
        for (int ks = 0; ks < 2; ks++) {
            uint32_t a[2][4];
#pragma unroll
            for (int mt2 = 0; mt2 < 2; mt2++) {
                int r = wm * 32 + mt2 * 16 + (lane & 15);
                int k8 = ks * 2 + (lane >> 4);
                ldsm4(a[mt2], ab + r * 64 + ((k8 ^ (r & 3)) << 4));
            }
            uint32_t bf[4][2];
#pragma unroll
            for (int ng = 0; ng < 2; ng++) {
                int r = ks * 16 + (lane & 15);
                int ch = wn * 4 + ng * 2 + (lane >> 4);
                uint32_t t[4];
                ldsm4t(t, bb + r * 256 + ((ch ^ (r & 15)) << 4));
                bf[ng * 2][0] = t[0]; bf[ng * 2][1] = t[1];
                bf[ng * 2 + 1][0] = t[2]; bf[ng * 2 + 1][1] = t[3];
            }
#pragma unroll
            for (int mt2 = 0; mt2 < 2; mt2++)
#pragma unroll
                for (int oct = 0; oct < 4; oct++)
                    mma16816(acc[mt2][oct], a[mt2], bf[oct]);
        }
        __syncthreads();
    }

    const int s_b = st * 64 + wm * 32 + (lane >> 2);
    const int d_b = nt * 128 + wn * 32 + (lane & 3) * 2;
#pragma unroll
    for (int mt2 = 0; mt2 < 2; mt2++) {
#pragma unroll
        for (int oct = 0; oct < 4; oct++) {
            int s = s_b + mt2 * 16, d = d_b + oct * 8;
            __half2 h01 = __floats2half2_rn(acc[mt2][oct][0], acc[mt2][oct][1]);
            __half2 h23 = __floats2half2_rn(acc[mt2][oct][2], acc[mt2][oct][3]);
            *reinterpret_cast<__half2*>(&g_Ah[(size_t)(s * Bc + b) * NIN + Dc + d]) = h01;
            *reinterpret_cast<__half2*>(&g_Ah[(size_t)((s + 8) * Bc + b) * NIN + Dc + d]) = h23;
        }
    }
}

// ---------------------------------------------------------------------------
// HMMA GEMM: U[4096,1024] = Ah @ Wh^T  (fp16 in, fp32 accum)
// ---------------------------------------------------------------------------
__device__ __forceinline__ void g_load(int c, int tid, uint32_t sb,
                                       int mt, int nt, int layer) {
    const int kc = c << 5;
    const __half* Ap = g_Ah + (size_t)(mt * 128) * NIN + kc;
    const __half* Bp = g_Wh + (size_t)(layer * NJ + nt * 128) * NIN + kc;
    const uint32_t ab = sb + (c % 3) * STAGE;
    const uint32_t bb = ab + STG_A;
#pragma unroll
    for (int i = 0; i < 2; i++) {
        int vi = tid + i * 256, r = vi >> 2, ch = vi & 3;
        cp16(ab + r * 64 + ((ch ^ (r & 3)) << 4), Ap + (size_t)r * NIN + ch * 8);
    }
#pragma unroll
    for (int i = 0; i < 2; i++) {
        int vi = tid + i * 256, r = vi >> 2, ch = vi & 3;
        cp16(bb + r * 64 + ((ch ^ (r & 3)) << 4), Bp + (size_t)r * NIN + ch * 8);
    }
}

__global__ void __launch_bounds__(256) k_wgemm(int layer) {
    __shared__ __align__(128) char sm[3 * STAGE];
    const uint32_t sb = smem_u32(sm);
    const int tid = threadIdx.x, wid = tid >> 5, lane = tid & 31;
    const int mt = blockIdx.x, nt = blockIdx.y;
    const int wm = wid & 3, wn = wid >> 2;

    float acc[2][8][4] = {};

    g_load(0, tid, sb, mt, nt, layer); CP_COMMIT();
    g_load(1, tid, sb, mt, nt, layer); CP_COMMIT();

    const int arow_b = wm * 32 + (lane & 15);
    const int brow_b = wn * 64 + (lane & 15);
    const int khalf = lane >> 4;

    for (int c = 0; c < NIT; c++) {
        if (c + 2 < NIT) g_load(c + 2, tid, sb, mt, nt, layer);
        CP_COMMIT();
        CP_WAIT2();
        __syncthreads();

        const uint32_t ab = sb + (c % 3) * STAGE;
        const uint32_t bb = ab + STG_A;
#pragma unroll
        for (int ks = 0; ks < 2; ks++) {
            const int k8 = ks * 2 + khalf;
            uint32_t a[2][4], b[8][2];
#pragma unroll
            for (int mtile = 0; mtile < 2; mtile++) {
                int r = arow_b + mtile * 16;
                ldsm4(a[mtile], ab + r * 64 + ((k8 ^ (r & 3)) << 4));
            }
#pragma unroll
            for (int np = 0; np < 4; np++) {
                int r = brow_b + np * 16;
                uint32_t t[4];
                ldsm4(t, bb + r * 64 + ((k8 ^ (r & 3)) << 4));
                b[np * 2][0] = t[0]; b[np * 2 + 1][0] = t[1];
                b[np * 2][1] = t[2]; b[np * 2 + 1][1] = t[3];
            }
#pragma unroll
            for (int mtile = 0; mtile < 2; mtile++)
#pragma unroll
                for (int ntile = 0; ntile < 8; ntile++)
                    mma16816(acc[mtile][ntile], a[mtile], b[ntile]);
        }
        __syncthreads();
    }

    const int m_b = mt * 128 + wm * 32 + (lane >> 2);
    const int n_b = nt * 128 + wn * 64 + (lane & 3) * 2;
#pragma unroll
    for (int mtile = 0; mtile < 2; mtile++) {
#pragma unroll
        for (int ntile = 0; ntile < 8; ntile++) {
            float* dst = g_U + (size_t)(m_b + mtile * 16) * NJ + n_b + ntile * 8;
            *reinterpret_cast<float2*>(dst) =
                make_float2(acc[mtile][ntile][0], acc[mtile][ntile][1]);
            *reinterpret_cast<float2*>(dst + 8 * NJ) =
                make_float2(acc[mtile][ntile][2], acc[mtile][ntile][3]);
        }
    }
}

// ---------------------------------------------------------------------------
// SRU chunked-parallel scan with batched prefetch
// ---------------------------------------------------------------------------
__global__ void k_scanA(const float* __restrict__ bfv, const float* __restrict__ bbv,
                        int layer) {
    const int ch = blockIdx.x, by = blockIdx.y;
    const int b = by >> 1, dir = by & 1;
    const int h = threadIdx.x;
    const float bf = ((dir == 0 ? bfv : bbv) + layer * 2 * Hc)[h];
    const float* base = g_U + ((size_t)(ch * CHS) * Bc + b) * NJ + dir * 512 + h;

    float u0v[CHS], ufv[CHS];
#pragma unroll
    for (int s = 0; s < CHS; s++) {
        const float* u = base + (size_t)s * (Bc * NJ);
        u0v[s] = u[0];
        ufv[s] = u[128];
    }
    float c = 0.0f, P = 1.0f;
#pragma unroll
    for (int s = 0; s < CHS; s++) {
        float f = sig_fast(ufv[s] + bf);
        c = u0v[s] + f * (c - u0v[s]);
        P *= f;
    }
    const int idx = (ch * 32 + by) * Hc + h;
    g_cend[idx] = c;
    g_P[idx] = P;
}

__global__ void k_scanC(const float* __restrict__ bfv, const float* __restrict__ bbv,
                        int layer, int is_last, float* __restrict__ out_final) {
    const int ch = blockIdx.x, by = blockIdx.y;
    const int b = by >> 1, dir = by & 1;
    const int h = threadIdx.x;
    const float* bias = (dir == 0 ? bfv : bbv) + layer * 2 * Hc;
    const float bf = bias[h];
    const float br = bias[Hc + h];
    const float* base = g_U + ((size_t)(ch * CHS) * Bc + b) * NJ + dir * 512 + h;

    // prefix compose: prefetch all (P, cend), then chain in registers
    float c = 0.0f;
    {
        float Pa[NCH - 1], Ca[NCH - 1];
#pragma unroll
        for (int i = 0; i < NCH - 1; i++) {
            if (i < ch) {
                const int idx = (i * 32 + by) * Hc + h;
                Pa[i] = g_P[idx];
                Ca[i] = g_cend[idx];
            }
        }
#pragma unroll
        for (int i = 0; i < NCH - 1; i++)
            if (i < ch) c = Pa[i] * c + Ca[i];
    }

#pragma unroll
    for (int half = 0; half < 2; half++) {
        float u0v[8], ufv[8], urv[8], hwv[8];
#pragma unroll
        for (int s = 0; s < 8; s++) {
            const float* u = base + (size_t)(half * 8 + s) * (Bc * NJ);
            u0v[s] = u[0]; ufv[s] = u[128]; urv[s] = u[256]; hwv[s] = u[384];
        }
#pragma unroll
        for (int s = 0; s < 8; s++) {
            float f = sig_fast(ufv[s] + bf);
            float r = sig_fast(urv[s] + br);
            c = u0v[s] + f * (c - u0v[s]);
            float hv = hwv[s] + r * (tanh_fast(c) - hwv[s]);
            const int s_abs = ch * CHS + half * 8 + s;
            if (is_last)
                out_final[b * (Sc * Dc) + s_abs * Dc + dir * Hc + h] = hv;
            else
                g_out[(s_abs * Bc + b) * Dc + dir * Hc + h] = hv;
        }
    }
}

// ---------------------------------------------------------------------------
extern "C" void kernel_launch(void* const* d_in, const int* in_sizes, int n_in,
                              void* d_out, int out_size) {
    const float* x            = (const float*)d_in[0];
    const unsigned char* mask = (const unsigned char*)d_in[1];
    const int* act            = (const int*)d_in[2];
    const float* w1           = (const float*)d_in[3];
    const float* b1           = (const float*)d_in[4];
    const float* w2           = (const float*)d_in[5];
    const float* b2           = (const float*)d_in[6];
    const float* v            = (const float*)d_in[7];
    const float* swf          = (const float*)d_in[8];
    const float* sbf          = (const float*)d_in[9];
    const float* swb          = (const float*)d_in[10];
    const float* sbb          = (const float*)d_in[11];
    float* out = (float*)d_out;

    k_xconv<<<Bc * Sc * Dc / 1024, 256>>>(x);
    k_wconv<<<dim3(16, 32, 2), dim3(32, 8)>>>(swf, swb);
    k_xt<<<dim3(Bc, 4), 256>>>(x, w1, b1, act);

    for (int layer = 0; layer < 2; layer++) {
        k_attn<<<dim3(Sc / GRP, Bc), 256>>>(x, layer == 0 ? 1 : 0, mask, act, w2, b2, v);
        k_pool<<<dim3(Bc, 4, 2), 256>>>();
        k_wgemm<<<dim3(32, 8), 256>>>(layer);
        k_scanA<<<dim3(NCH, 32), Hc>>>(sbf, sbb, layer);
        k_scanC<<<dim3(NCH, 32), Hc>>>(sbf, sbb, layer, layer == 1 ? 1 : 0, out);
    }
}